// round 1
// baseline (speedup 1.0000x reference)
#include <cuda_runtime.h>
#include <cstdint>

#define BATCH 8
#define SEQ   1024
#define DIM   1024
#define NH    16
#define HD    64

// Scratch: Q,V as [b*h][s][hd]; K pre-transposed as [b*h][hd][s]
__device__ float g_q [BATCH*NH*SEQ*HD];
__device__ float g_kt[BATCH*NH*HD*SEQ];
__device__ float g_v [BATCH*NH*SEQ*HD];

// ---------------------------------------------------------------------------
// Kernel 1: fused QKV projection GEMM.
//   Y = x @ W,  M=8192, N=1024, K=1024.  blockIdx.z selects Wq/Wk/Wv.
//   Tile 64x64, BK=16, 256 threads, 4x4 micro-tile.
//   Q,V written as [bh][s][hd]; K written transposed [bh][hd][s].
// ---------------------------------------------------------------------------
__global__ __launch_bounds__(256) void qkv_gemm_kernel(
    const float* __restrict__ x,
    const float* __restrict__ Wq,
    const float* __restrict__ Wk,
    const float* __restrict__ Wv)
{
    const int z = blockIdx.z;
    const float* __restrict__ W = (z == 0) ? Wq : (z == 1 ? Wk : Wv);

    __shared__ float Ast[16][64];   // [k][m] (transposed for float4 a-frag)
    __shared__ float Bs [16][64];   // [k][n]

    const int m0  = blockIdx.x * 64;
    const int h   = blockIdx.y;          // head -> n0 = h*64
    const int tid = threadIdx.x;
    const int ty  = tid >> 4, tx = tid & 15;
    const int ty4 = ty * 4,  tx4 = tx * 4;

    const int arow = tid >> 2, acol4 = (tid & 3) * 4;   // A tile: 64 x 16
    const int brow = tid >> 4, bcol4 = (tid & 15) * 4;  // B tile: 16 x 64

    const float* Aptr = x + (size_t)(m0 + arow) * DIM + acol4;
    const float* Bptr = W + (size_t)brow * DIM + h * 64 + bcol4;

    float acc[4][4] = {};

    for (int k0 = 0; k0 < DIM; k0 += 16) {
        float4 a  = *(const float4*)(Aptr + k0);
        float4 bv = *(const float4*)(Bptr + (size_t)k0 * DIM);
        Ast[acol4 + 0][arow] = a.x;
        Ast[acol4 + 1][arow] = a.y;
        Ast[acol4 + 2][arow] = a.z;
        Ast[acol4 + 3][arow] = a.w;
        *(float4*)&Bs[brow][bcol4] = bv;
        __syncthreads();

        #pragma unroll
        for (int kk = 0; kk < 16; kk++) {
            float4 av  = *(float4*)&Ast[kk][ty4];
            float4 bvv = *(float4*)&Bs [kk][tx4];
            float aa[4] = {av.x, av.y, av.z, av.w};
            float bb[4] = {bvv.x, bvv.y, bvv.z, bvv.w};
            #pragma unroll
            for (int ii = 0; ii < 4; ii++)
                #pragma unroll
                for (int jj = 0; jj < 4; jj++)
                    acc[ii][jj] += aa[ii] * bb[jj];
        }
        __syncthreads();
    }

    const int b      = m0 >> 10;              // block never straddles batches
    const int s_base = (m0 & 1023) + ty4;
    const int bh     = b * NH + h;

    if (z == 1) {
        // K transposed: g_kt[bh][hd][s]
        float* base = g_kt + (size_t)bh * HD * SEQ;
        #pragma unroll
        for (int ii = 0; ii < 4; ii++)
            #pragma unroll
            for (int jj = 0; jj < 4; jj++)
                base[(size_t)(tx4 + jj) * SEQ + (s_base + ii)] = acc[ii][jj];
    } else {
        float* base = (z == 0 ? g_q : g_v) + (size_t)bh * SEQ * HD;
        #pragma unroll
        for (int ii = 0; ii < 4; ii++) {
            float4 o = make_float4(acc[ii][0], acc[ii][1], acc[ii][2], acc[ii][3]);
            *(float4*)&base[(size_t)(s_base + ii) * HD + tx4] = o;
        }
    }
}

// ---------------------------------------------------------------------------
// Kernel 2: single-pass attention (unsafe softmax -> no running max needed).
//   block = 64 query rows x one (b,h). 256 threads, 4x4 micro-tiles.
//   smem: Qs(transposed [d][i]) 16K | KP (K^T tile, reused as P tile) 16K |
//         Vs 16K  => exactly 48KB static.
//   Row denominators live in registers (warp butterfly over the 16-lane
//   tx-group), no smem reduction.
// ---------------------------------------------------------------------------
__global__ __launch_bounds__(256) void attn_kernel(
    const float* __restrict__ mask, float* __restrict__ out)
{
    __shared__ float Qs[64 * 64];   // [d][i]
    __shared__ float KP[64 * 64];   // K^T tile [d][j], then P tile [i][t]
    __shared__ float Vs[64 * 64];   // [t][j]

    const int qt = blockIdx.x;      // query tile (0..15)
    const int bh = blockIdx.y;      // 0..127
    const int b  = bh >> 4, h = bh & 15;

    const float* Q  = g_q  + (size_t)bh * SEQ * HD;
    const float* Kt = g_kt + (size_t)bh * HD * SEQ;
    const float* V  = g_v  + (size_t)bh * SEQ * HD;
    const float* M  = mask + (size_t)b * SEQ * SEQ;

    const int tid = threadIdx.x;
    const int ty  = tid >> 4, tx = tid & 15;
    const int ty4 = ty * 4,  tx4 = tx * 4;

    // Load Q tile transposed into smem: Qs[d][i]
    for (int i = tid; i < 1024; i += 256) {
        int r = i >> 4, c4 = (i & 15) << 2;
        float4 q4 = *(const float4*)&Q[(size_t)(qt * 64 + r) * HD + c4];
        Qs[(c4 + 0) * 64 + r] = q4.x;
        Qs[(c4 + 1) * 64 + r] = q4.y;
        Qs[(c4 + 2) * 64 + r] = q4.z;
        Qs[(c4 + 3) * 64 + r] = q4.w;
    }

    float ctx[4][4] = {};
    float dsum[4]   = {0.f, 0.f, 0.f, 0.f};

    for (int kt = 0; kt < 16; kt++) {
        __syncthreads();   // protect KP/Vs from previous iteration readers
        // K^T tile (coalesced, conflict-free) and V tile
        for (int i = tid; i < 1024; i += 256) {
            int r = i >> 4, c4 = (i & 15) << 2;
            *(float4*)&KP[r * 64 + c4] =
                *(const float4*)&Kt[(size_t)r * SEQ + kt * 64 + c4];
            *(float4*)&Vs[r * 64 + c4] =
                *(const float4*)&V [(size_t)(kt * 64 + r) * HD + c4];
        }
        __syncthreads();

        // scores = Q K^T (accumulate over d)
        float sc[4][4] = {};
        #pragma unroll 8
        for (int d = 0; d < 64; d++) {
            float4 aq = *(float4*)&Qs[d * 64 + ty4];
            float4 bk = *(float4*)&KP[d * 64 + tx4];
            float aa[4] = {aq.x, aq.y, aq.z, aq.w};
            float bb[4] = {bk.x, bk.y, bk.z, bk.w};
            #pragma unroll
            for (int ii = 0; ii < 4; ii++)
                #pragma unroll
                for (int jj = 0; jj < 4; jj++)
                    sc[ii][jj] += aa[ii] * bb[jj];
        }

        // e = exp(sc/8) * mask ; per-row denom via butterfly over tx group
        float e[4][4];
        #pragma unroll
        for (int ii = 0; ii < 4; ii++) {
            float4 m4 = *(const float4*)
                &M[(size_t)(qt * 64 + ty4 + ii) * SEQ + kt * 64 + tx4];
            e[ii][0] = __expf(sc[ii][0] * 0.125f) * m4.x;
            e[ii][1] = __expf(sc[ii][1] * 0.125f) * m4.y;
            e[ii][2] = __expf(sc[ii][2] * 0.125f) * m4.z;
            e[ii][3] = __expf(sc[ii][3] * 0.125f) * m4.w;
            float rs = e[ii][0] + e[ii][1] + e[ii][2] + e[ii][3];
            rs += __shfl_xor_sync(0xffffffffu, rs, 8);
            rs += __shfl_xor_sync(0xffffffffu, rs, 4);
            rs += __shfl_xor_sync(0xffffffffu, rs, 2);
            rs += __shfl_xor_sync(0xffffffffu, rs, 1);
            dsum[ii] += rs;
        }

        __syncthreads();   // everyone done reading KP as K^T
        #pragma unroll
        for (int ii = 0; ii < 4; ii++) {
            float4 o = make_float4(e[ii][0], e[ii][1], e[ii][2], e[ii][3]);
            *(float4*)&KP[(ty4 + ii) * 64 + tx4] = o;   // P tile [i][t]
        }
        __syncthreads();

        // ctx += P @ V
        #pragma unroll 8
        for (int t = 0; t < 64; t++) {
            float a0 = KP[(ty4 + 0) * 64 + t];
            float a1 = KP[(ty4 + 1) * 64 + t];
            float a2 = KP[(ty4 + 2) * 64 + t];
            float a3 = KP[(ty4 + 3) * 64 + t];
            float4 bv = *(float4*)&Vs[t * 64 + tx4];
            ctx[0][0] += a0 * bv.x; ctx[0][1] += a0 * bv.y;
            ctx[0][2] += a0 * bv.z; ctx[0][3] += a0 * bv.w;
            ctx[1][0] += a1 * bv.x; ctx[1][1] += a1 * bv.y;
            ctx[1][2] += a1 * bv.z; ctx[1][3] += a1 * bv.w;
            ctx[2][0] += a2 * bv.x; ctx[2][1] += a2 * bv.y;
            ctx[2][2] += a2 * bv.z; ctx[2][3] += a2 * bv.w;
            ctx[3][0] += a3 * bv.x; ctx[3][1] += a3 * bv.y;
            ctx[3][2] += a3 * bv.z; ctx[3][3] += a3 * bv.w;
        }
    }

    // out[b][s][h][hd] = ctx / (denom + 1e-8)
    const int orow = qt * 64 + ty4;
    #pragma unroll
    for (int ii = 0; ii < 4; ii++) {
        float inv = 1.0f / (dsum[ii] + 1e-8f);
        float4 o = make_float4(ctx[ii][0] * inv, ctx[ii][1] * inv,
                               ctx[ii][2] * inv, ctx[ii][3] * inv);
        *(float4*)&out[(((size_t)b * SEQ + orow + ii) * NH + h) * HD + tx4] = o;
    }
}

// ---------------------------------------------------------------------------
extern "C" void kernel_launch(void* const* d_in, const int* in_sizes, int n_in,
                              void* d_out, int out_size)
{
    const float* x    = (const float*)d_in[0];
    const float* mask = (const float*)d_in[1];
    const float* Wq   = (const float*)d_in[2];
    const float* Wk   = (const float*)d_in[3];
    const float* Wv   = (const float*)d_in[4];
    float* out = (float*)d_out;

    qkv_gemm_kernel<<<dim3(128, 16, 3), 256>>>(x, Wq, Wk, Wv);
    attn_kernel<<<dim3(16, 128), 256>>>(mask, out);
}

// round 3
// speedup vs baseline: 1.5243x; 1.5243x over previous
#include <cuda_runtime.h>
#include <cuda_bf16.h>
#include <cstdint>

#define BATCH 8
#define SEQ   1024
#define DIM   1024
#define NH    16
#define HD    64

// fp32 scratch consumed by attention kernel
__device__ float g_q [BATCH*NH*SEQ*HD];
__device__ float g_kt[BATCH*NH*HD*SEQ];
__device__ float g_v [BATCH*NH*SEQ*HD];

// split-bf16 operands for MMA projections
__device__ __nv_bfloat16 g_xh[BATCH*SEQ*DIM];     // x hi   [m][k]
__device__ __nv_bfloat16 g_xl[BATCH*SEQ*DIM];     // x lo
__device__ __nv_bfloat16 g_wth[3*DIM*DIM];        // W^T hi [n][k]
__device__ __nv_bfloat16 g_wtl[3*DIM*DIM];        // W^T lo

// ---------------------------------------------------------------------------
// helpers
// ---------------------------------------------------------------------------
__device__ __forceinline__ uint32_t smem_u32(const void* p) {
    uint32_t a;
    asm("{ .reg .u64 t; cvta.to.shared.u64 t, %1; cvt.u32.u64 %0, t; }"
        : "=r"(a) : "l"(p));
    return a;
}
__device__ __forceinline__ void ldsm_x4(uint32_t a[4], uint32_t addr) {
    asm volatile("ldmatrix.sync.aligned.m8n8.x4.shared.b16 {%0,%1,%2,%3}, [%4];"
                 : "=r"(a[0]), "=r"(a[1]), "=r"(a[2]), "=r"(a[3]) : "r"(addr));
}
__device__ __forceinline__ void ldsm_x2(uint32_t b[2], uint32_t addr) {
    asm volatile("ldmatrix.sync.aligned.m8n8.x2.shared.b16 {%0,%1}, [%2];"
                 : "=r"(b[0]), "=r"(b[1]) : "r"(addr));
}
__device__ __forceinline__ void mma_bf16(float c[4], const uint32_t a[4],
                                         const uint32_t b[2]) {
    asm volatile(
        "mma.sync.aligned.m16n8k16.row.col.f32.bf16.bf16.f32 "
        "{%0,%1,%2,%3}, {%4,%5,%6,%7}, {%8,%9}, {%0,%1,%2,%3};"
        : "+f"(c[0]), "+f"(c[1]), "+f"(c[2]), "+f"(c[3])
        : "r"(a[0]), "r"(a[1]), "r"(a[2]), "r"(a[3]), "r"(b[0]), "r"(b[1]));
}

// ---------------------------------------------------------------------------
// Preprocess: split x -> (hi, lo) bf16
// ---------------------------------------------------------------------------
__global__ __launch_bounds__(256) void convert_x_kernel(const float* __restrict__ x) {
    int i = (blockIdx.x * 256 + threadIdx.x) * 4;
    float4 v = *(const float4*)(x + i);
    __nv_bfloat16 h0 = __float2bfloat16(v.x), h1 = __float2bfloat16(v.y);
    __nv_bfloat16 h2 = __float2bfloat16(v.z), h3 = __float2bfloat16(v.w);
    __nv_bfloat162 hi01, hi23, lo01, lo23;
    hi01.x = h0; hi01.y = h1; hi23.x = h2; hi23.y = h3;
    lo01.x = __float2bfloat16(v.x - __bfloat162float(h0));
    lo01.y = __float2bfloat16(v.y - __bfloat162float(h1));
    lo23.x = __float2bfloat16(v.z - __bfloat162float(h2));
    lo23.y = __float2bfloat16(v.w - __bfloat162float(h3));
    *(__nv_bfloat162*)(g_xh + i)     = hi01;
    *(__nv_bfloat162*)(g_xh + i + 2) = hi23;
    *(__nv_bfloat162*)(g_xl + i)     = lo01;
    *(__nv_bfloat162*)(g_xl + i + 2) = lo23;
}

// Preprocess: W[k][n] -> Wt[n][k] split into (hi, lo) bf16, tiled transpose
__global__ __launch_bounds__(256) void convert_wt_kernel(
    const float* __restrict__ Wq, const float* __restrict__ Wk,
    const float* __restrict__ Wv)
{
    __shared__ float t[32][33];
    const int z = blockIdx.z;
    const float* __restrict__ W = (z == 0) ? Wq : (z == 1 ? Wk : Wv);
    const int n0 = blockIdx.x * 32, k0 = blockIdx.y * 32;
    const int tx = threadIdx.x, ty = threadIdx.y;   // block (32, 8)

    #pragma unroll
    for (int i = ty; i < 32; i += 8)
        t[i][tx] = W[(size_t)(k0 + i) * DIM + n0 + tx];
    __syncthreads();

    __nv_bfloat16* wh = g_wth + (size_t)z * DIM * DIM;
    __nv_bfloat16* wl = g_wtl + (size_t)z * DIM * DIM;
    #pragma unroll
    for (int i = ty; i < 32; i += 8) {
        float v = t[tx][i];                        // = W[k0+tx][n0+i]
        __nv_bfloat16 h = __float2bfloat16(v);
        wh[(size_t)(n0 + i) * DIM + k0 + tx] = h;
        wl[(size_t)(n0 + i) * DIM + k0 + tx] = __float2bfloat16(v - __bfloat162float(h));
    }
}

// ---------------------------------------------------------------------------
// QKV projection GEMM via mma.sync bf16 (split hi/lo, 3 products).
//   Block: 128x128 tile, 256 threads (8 warps, 2x4), warp tile 64x32, BK=32.
//   A = x_hi/lo [m][k], B = Wt_hi/lo [n][k] (k contiguous = col-major k x n).
// ---------------------------------------------------------------------------
#define BK 32
#define LDS 40      // padded row stride (bf16 elems): 32 + 8

__global__ __launch_bounds__(256, 1) void qkv_mma_kernel()
{
    __shared__ __nv_bfloat16 sm[4][128 * LDS];   // Ah, Al, Bh, Bl

    const int tid  = threadIdx.x;
    const int w    = tid >> 5, lane = tid & 31;
    const int wm   = w >> 2, wn = w & 3;         // warp grid 2 x 4
    const int m0   = blockIdx.x * 128;
    const int n0   = blockIdx.y * 128;
    const int z    = blockIdx.z;

    const __nv_bfloat16* __restrict__ srcs[4] = {
        g_xh + (size_t)m0 * DIM,
        g_xl + (size_t)m0 * DIM,
        g_wth + (size_t)z * DIM * DIM + (size_t)n0 * DIM,
        g_wtl + (size_t)z * DIM * DIM + (size_t)n0 * DIM
    };

    // smem byte addresses for ldmatrix
    uint32_t smb[4];
    #pragma unroll
    for (int t = 0; t < 4; t++) smb[t] = smem_u32(sm[t]);

    // A-frag row/col (per lane): row lane%16, col-half lane/16
    const int a_row = lane & 15, a_kh = (lane >> 4) * 8;
    // B-frag row/col: row lane%8, col-half (lane/8)&1
    const int b_row = lane & 7,  b_kh = ((lane >> 3) & 1) * 8;

    float acc[4][4][4] = {};   // [mtile][ntile][4]

    const int ld_r = tid >> 2;            // 0..63 (two rows per thread: +64)
    const int ld_c = (tid & 3) * 8;       // bf16 col

    for (int k0 = 0; k0 < DIM; k0 += BK) {
        __syncthreads();
        #pragma unroll
        for (int t = 0; t < 4; t++) {
            const __nv_bfloat16* s = srcs[t] + k0;
            *(uint4*)&sm[t][ld_r * LDS + ld_c] =
                *(const uint4*)(s + (size_t)ld_r * DIM + ld_c);
            *(uint4*)&sm[t][(ld_r + 64) * LDS + ld_c] =
                *(const uint4*)(s + (size_t)(ld_r + 64) * DIM + ld_c);
        }
        __syncthreads();

        #pragma unroll
        for (int kk = 0; kk < BK; kk += 16) {
            uint32_t ah[4][4], al[4][4];
            #pragma unroll
            for (int mt = 0; mt < 4; mt++) {
                int roff = (wm * 64 + mt * 16 + a_row) * LDS + kk + a_kh;
                ldsm_x4(ah[mt], smb[0] + roff * 2);
                ldsm_x4(al[mt], smb[1] + roff * 2);
            }
            uint32_t bh[4][2], bl[4][2];
            #pragma unroll
            for (int nt = 0; nt < 4; nt++) {
                int roff = (wn * 32 + nt * 8 + b_row) * LDS + kk + b_kh;
                ldsm_x2(bh[nt], smb[2] + roff * 2);
                ldsm_x2(bl[nt], smb[3] + roff * 2);
            }
            #pragma unroll
            for (int mt = 0; mt < 4; mt++)
                #pragma unroll
                for (int nt = 0; nt < 4; nt++) {
                    mma_bf16(acc[mt][nt], ah[mt], bh[nt]);
                    mma_bf16(acc[mt][nt], ah[mt], bl[nt]);
                    mma_bf16(acc[mt][nt], al[mt], bh[nt]);
                }
        }
    }

    // epilogue: C layout c0=(m=lane/4, n=2*(lane%4)), c1 n+1, c2/c3 m+8
    const int em = lane >> 2, en = (lane & 3) * 2;
    #pragma unroll
    for (int mt = 0; mt < 4; mt++) {
        #pragma unroll
        for (int nt = 0; nt < 4; nt++) {
            int mg0 = m0 + wm * 64 + mt * 16 + em;
            int ng  = n0 + wn * 32 + nt * 8 + en;
            int h = ng >> 6, hd = ng & 63;
            #pragma unroll
            for (int half = 0; half < 2; half++) {
                int mg = mg0 + half * 8;
                int b = mg >> 10, s = mg & 1023;
                int bh_i = b * NH + h;
                float c0 = acc[mt][nt][half * 2 + 0];
                float c1 = acc[mt][nt][half * 2 + 1];
                if (z == 1) {
                    float* dst = g_kt + ((size_t)bh_i * HD + hd) * SEQ + s;
                    dst[0]   = c0;
                    dst[SEQ] = c1;
                } else {
                    float* dst = ((z == 0) ? g_q : g_v)
                                 + ((size_t)bh_i * SEQ + s) * HD + hd;
                    *(float2*)dst = make_float2(c0, c1);
                }
            }
        }
    }
}

// ---------------------------------------------------------------------------
// Attention kernel (unchanged fp32 path from round 1)
// ---------------------------------------------------------------------------
__global__ __launch_bounds__(256) void attn_kernel(
    const float* __restrict__ mask, float* __restrict__ out)
{
    __shared__ float Qs[64 * 64];
    __shared__ float KP[64 * 64];
    __shared__ float Vs[64 * 64];

    const int qt = blockIdx.x;
    const int bh = blockIdx.y;
    const int b  = bh >> 4, h = bh & 15;

    const float* Q  = g_q  + (size_t)bh * SEQ * HD;
    const float* Kt = g_kt + (size_t)bh * HD * SEQ;
    const float* V  = g_v  + (size_t)bh * SEQ * HD;
    const float* M  = mask + (size_t)b * SEQ * SEQ;

    const int tid = threadIdx.x;
    const int ty  = tid >> 4, tx = tid & 15;
    const int ty4 = ty * 4,  tx4 = tx * 4;

    for (int i = tid; i < 1024; i += 256) {
        int r = i >> 4, c4 = (i & 15) << 2;
        float4 q4 = *(const float4*)&Q[(size_t)(qt * 64 + r) * HD + c4];
        Qs[(c4 + 0) * 64 + r] = q4.x;
        Qs[(c4 + 1) * 64 + r] = q4.y;
        Qs[(c4 + 2) * 64 + r] = q4.z;
        Qs[(c4 + 3) * 64 + r] = q4.w;
    }

    float ctx[4][4] = {};
    float dsum[4]   = {0.f, 0.f, 0.f, 0.f};

    for (int kt = 0; kt < 16; kt++) {
        __syncthreads();
        for (int i = tid; i < 1024; i += 256) {
            int r = i >> 4, c4 = (i & 15) << 2;
            *(float4*)&KP[r * 64 + c4] =
                *(const float4*)&Kt[(size_t)r * SEQ + kt * 64 + c4];
            *(float4*)&Vs[r * 64 + c4] =
                *(const float4*)&V [(size_t)(kt * 64 + r) * HD + c4];
        }
        __syncthreads();

        float sc[4][4] = {};
        #pragma unroll 8
        for (int d = 0; d < 64; d++) {
            float4 aq = *(float4*)&Qs[d * 64 + ty4];
            float4 bk = *(float4*)&KP[d * 64 + tx4];
            float aa[4] = {aq.x, aq.y, aq.z, aq.w};
            float bb[4] = {bk.x, bk.y, bk.z, bk.w};
            #pragma unroll
            for (int ii = 0; ii < 4; ii++)
                #pragma unroll
                for (int jj = 0; jj < 4; jj++)
                    sc[ii][jj] += aa[ii] * bb[jj];
        }

        float e[4][4];
        #pragma unroll
        for (int ii = 0; ii < 4; ii++) {
            float4 m4 = *(const float4*)
                &M[(size_t)(qt * 64 + ty4 + ii) * SEQ + kt * 64 + tx4];
            e[ii][0] = __expf(sc[ii][0] * 0.125f) * m4.x;
            e[ii][1] = __expf(sc[ii][1] * 0.125f) * m4.y;
            e[ii][2] = __expf(sc[ii][2] * 0.125f) * m4.z;
            e[ii][3] = __expf(sc[ii][3] * 0.125f) * m4.w;
            float rs = e[ii][0] + e[ii][1] + e[ii][2] + e[ii][3];
            rs += __shfl_xor_sync(0xffffffffu, rs, 8);
            rs += __shfl_xor_sync(0xffffffffu, rs, 4);
            rs += __shfl_xor_sync(0xffffffffu, rs, 2);
            rs += __shfl_xor_sync(0xffffffffu, rs, 1);
            dsum[ii] += rs;
        }

        __syncthreads();
        #pragma unroll
        for (int ii = 0; ii < 4; ii++) {
            float4 o = make_float4(e[ii][0], e[ii][1], e[ii][2], e[ii][3]);
            *(float4*)&KP[(ty4 + ii) * 64 + tx4] = o;
        }
        __syncthreads();

        #pragma unroll 8
        for (int t = 0; t < 64; t++) {
            float a0 = KP[(ty4 + 0) * 64 + t];
            float a1 = KP[(ty4 + 1) * 64 + t];
            float a2 = KP[(ty4 + 2) * 64 + t];
            float a3 = KP[(ty4 + 3) * 64 + t];
            float4 bv = *(float4*)&Vs[t * 64 + tx4];
            ctx[0][0] += a0 * bv.x; ctx[0][1] += a0 * bv.y;
            ctx[0][2] += a0 * bv.z; ctx[0][3] += a0 * bv.w;
            ctx[1][0] += a1 * bv.x; ctx[1][1] += a1 * bv.y;
            ctx[1][2] += a1 * bv.z; ctx[1][3] += a1 * bv.w;
            ctx[2][0] += a2 * bv.x; ctx[2][1] += a2 * bv.y;
            ctx[2][2] += a2 * bv.z; ctx[2][3] += a2 * bv.w;
            ctx[3][0] += a3 * bv.x; ctx[3][1] += a3 * bv.y;
            ctx[3][2] += a3 * bv.z; ctx[3][3] += a3 * bv.w;
        }
    }

    const int orow = qt * 64 + ty4;
    #pragma unroll
    for (int ii = 0; ii < 4; ii++) {
        float inv = 1.0f / (dsum[ii] + 1e-8f);
        float4 o = make_float4(ctx[ii][0] * inv, ctx[ii][1] * inv,
                               ctx[ii][2] * inv, ctx[ii][3] * inv);
        *(float4*)&out[(((size_t)b * SEQ + orow + ii) * NH + h) * HD + tx4] = o;
    }
}

// ---------------------------------------------------------------------------
extern "C" void kernel_launch(void* const* d_in, const int* in_sizes, int n_in,
                              void* d_out, int out_size)
{
    const float* x    = (const float*)d_in[0];
    const float* mask = (const float*)d_in[1];
    const float* Wq   = (const float*)d_in[2];
    const float* Wk   = (const float*)d_in[3];
    const float* Wv   = (const float*)d_in[4];
    float* out = (float*)d_out;

    convert_x_kernel<<<BATCH * SEQ, 256>>>(x);
    convert_wt_kernel<<<dim3(32, 32, 3), dim3(32, 8)>>>(Wq, Wk, Wv);
    qkv_mma_kernel<<<dim3(64, 8, 3), 256>>>();
    attn_kernel<<<dim3(16, 128), 256>>>(mask, out);
}

// round 4
// speedup vs baseline: 2.1263x; 1.3950x over previous
#include <cuda_runtime.h>
#include <cuda_bf16.h>
#include <cstdint>

#define BATCH 8
#define SEQ   1024
#define DIM   1024
#define NH    16
#define HD    64

// split-bf16 operands for MMA projections
__device__ __nv_bfloat16 g_xh[BATCH*SEQ*DIM];     // x hi   [m][k]
__device__ __nv_bfloat16 g_xl[BATCH*SEQ*DIM];     // x lo
__device__ __nv_bfloat16 g_wth[3*DIM*DIM];        // W^T hi [n][k]
__device__ __nv_bfloat16 g_wtl[3*DIM*DIM];        // W^T lo

// attention operands (written by QKV GEMM epilogue)
__device__ __nv_bfloat16 g_qh [BATCH*NH*SEQ*HD];  // Q hi  [bh][s][hd]
__device__ __nv_bfloat16 g_ql [BATCH*NH*SEQ*HD];
__device__ __nv_bfloat16 g_kh [BATCH*NH*SEQ*HD];  // K hi  [bh][s][hd]
__device__ __nv_bfloat16 g_kl [BATCH*NH*SEQ*HD];
__device__ __nv_bfloat16 g_vth[BATCH*NH*HD*SEQ];  // V^T hi [bh][hd][s]
__device__ __nv_bfloat16 g_vtl[BATCH*NH*HD*SEQ];

// ---------------------------------------------------------------------------
// helpers
// ---------------------------------------------------------------------------
__device__ __forceinline__ uint32_t smem_u32(const void* p) {
    uint32_t a;
    asm("{ .reg .u64 t; cvta.to.shared.u64 t, %1; cvt.u32.u64 %0, t; }"
        : "=r"(a) : "l"(p));
    return a;
}
__device__ __forceinline__ void ldsm_x4(uint32_t a[4], uint32_t addr) {
    asm volatile("ldmatrix.sync.aligned.m8n8.x4.shared.b16 {%0,%1,%2,%3}, [%4];"
                 : "=r"(a[0]), "=r"(a[1]), "=r"(a[2]), "=r"(a[3]) : "r"(addr));
}
__device__ __forceinline__ void ldsm_x2(uint32_t b[2], uint32_t addr) {
    asm volatile("ldmatrix.sync.aligned.m8n8.x2.shared.b16 {%0,%1}, [%2];"
                 : "=r"(b[0]), "=r"(b[1]) : "r"(addr));
}
__device__ __forceinline__ void mma_bf16(float c[4], const uint32_t a[4],
                                         const uint32_t b[2]) {
    asm volatile(
        "mma.sync.aligned.m16n8k16.row.col.f32.bf16.bf16.f32 "
        "{%0,%1,%2,%3}, {%4,%5,%6,%7}, {%8,%9}, {%0,%1,%2,%3};"
        : "+f"(c[0]), "+f"(c[1]), "+f"(c[2]), "+f"(c[3])
        : "r"(a[0]), "r"(a[1]), "r"(a[2]), "r"(a[3]), "r"(b[0]), "r"(b[1]));
}
__device__ __forceinline__ uint32_t pack_bf16(__nv_bfloat16 a, __nv_bfloat16 b) {
    __nv_bfloat162 p; p.x = a; p.y = b;
    return *(uint32_t*)&p;
}
// exp(s/8) via exp2 poly: t = s*log2e/8; magic round; degree-5 Taylor on [-.5,.5]
__device__ __forceinline__ float fexp8(float s) {
    float t = s * 0.18033688011112042f;          // log2(e)/8
    float k = t + 12582912.0f;                   // 1.5*2^23 magic round
    float j = k - 12582912.0f;
    float f = t - j;
    float p = 1.3333558147e-3f;
    p = fmaf(p, f, 9.6181291076e-3f);
    p = fmaf(p, f, 5.5504108665e-2f);
    p = fmaf(p, f, 2.4022650696e-1f);
    p = fmaf(p, f, 6.9314718056e-1f);
    p = fmaf(p, f, 1.0f);
    int ib = __float_as_int(k) - 0x4B400000;     // integer part of t
    float scale = __int_as_float((ib + 127) << 23);
    return p * scale;
}

// ---------------------------------------------------------------------------
// Preprocess: split x -> (hi, lo) bf16
// ---------------------------------------------------------------------------
__global__ __launch_bounds__(256) void convert_x_kernel(const float* __restrict__ x) {
    int i = (blockIdx.x * 256 + threadIdx.x) * 4;
    float4 v = *(const float4*)(x + i);
    __nv_bfloat16 h0 = __float2bfloat16(v.x), h1 = __float2bfloat16(v.y);
    __nv_bfloat16 h2 = __float2bfloat16(v.z), h3 = __float2bfloat16(v.w);
    __nv_bfloat162 hi01, hi23, lo01, lo23;
    hi01.x = h0; hi01.y = h1; hi23.x = h2; hi23.y = h3;
    lo01.x = __float2bfloat16(v.x - __bfloat162float(h0));
    lo01.y = __float2bfloat16(v.y - __bfloat162float(h1));
    lo23.x = __float2bfloat16(v.z - __bfloat162float(h2));
    lo23.y = __float2bfloat16(v.w - __bfloat162float(h3));
    *(__nv_bfloat162*)(g_xh + i)     = hi01;
    *(__nv_bfloat162*)(g_xh + i + 2) = hi23;
    *(__nv_bfloat162*)(g_xl + i)     = lo01;
    *(__nv_bfloat162*)(g_xl + i + 2) = lo23;
}

// Preprocess: W[k][n] -> Wt[n][k] split into (hi, lo) bf16
__global__ __launch_bounds__(256) void convert_wt_kernel(
    const float* __restrict__ Wq, const float* __restrict__ Wk,
    const float* __restrict__ Wv)
{
    __shared__ float t[32][33];
    const int z = blockIdx.z;
    const float* __restrict__ W = (z == 0) ? Wq : (z == 1 ? Wk : Wv);
    const int n0 = blockIdx.x * 32, k0 = blockIdx.y * 32;
    const int tx = threadIdx.x, ty = threadIdx.y;   // block (32, 8)

    #pragma unroll
    for (int i = ty; i < 32; i += 8)
        t[i][tx] = W[(size_t)(k0 + i) * DIM + n0 + tx];
    __syncthreads();

    __nv_bfloat16* wh = g_wth + (size_t)z * DIM * DIM;
    __nv_bfloat16* wl = g_wtl + (size_t)z * DIM * DIM;
    #pragma unroll
    for (int i = ty; i < 32; i += 8) {
        float v = t[tx][i];
        __nv_bfloat16 h = __float2bfloat16(v);
        wh[(size_t)(n0 + i) * DIM + k0 + tx] = h;
        wl[(size_t)(n0 + i) * DIM + k0 + tx] = __float2bfloat16(v - __bfloat162float(h));
    }
}

// ---------------------------------------------------------------------------
// QKV projection GEMM via mma.sync bf16 (split hi/lo, 3 products).
//   Epilogue writes bf16 hi/lo: Q,K row-major [bh][s][hd]; V transposed [bh][hd][s].
// ---------------------------------------------------------------------------
#define BK 32
#define LDS 40

__global__ __launch_bounds__(256, 1) void qkv_mma_kernel()
{
    __shared__ __nv_bfloat16 sm[4][128 * LDS];   // Ah, Al, Bh, Bl

    const int tid  = threadIdx.x;
    const int w    = tid >> 5, lane = tid & 31;
    const int wm   = w >> 2, wn = w & 3;         // warp grid 2 x 4
    const int m0   = blockIdx.x * 128;
    const int n0   = blockIdx.y * 128;
    const int z    = blockIdx.z;

    const __nv_bfloat16* __restrict__ srcs[4] = {
        g_xh + (size_t)m0 * DIM,
        g_xl + (size_t)m0 * DIM,
        g_wth + (size_t)z * DIM * DIM + (size_t)n0 * DIM,
        g_wtl + (size_t)z * DIM * DIM + (size_t)n0 * DIM
    };

    uint32_t smb[4];
    #pragma unroll
    for (int t = 0; t < 4; t++) smb[t] = smem_u32(sm[t]);

    const int a_row = lane & 15, a_kh = (lane >> 4) * 8;
    const int b_row = lane & 7,  b_kh = ((lane >> 3) & 1) * 8;

    float acc[4][4][4] = {};

    const int ld_r = tid >> 2;
    const int ld_c = (tid & 3) * 8;

    for (int k0 = 0; k0 < DIM; k0 += BK) {
        __syncthreads();
        #pragma unroll
        for (int t = 0; t < 4; t++) {
            const __nv_bfloat16* s = srcs[t] + k0;
            *(uint4*)&sm[t][ld_r * LDS + ld_c] =
                *(const uint4*)(s + (size_t)ld_r * DIM + ld_c);
            *(uint4*)&sm[t][(ld_r + 64) * LDS + ld_c] =
                *(const uint4*)(s + (size_t)(ld_r + 64) * DIM + ld_c);
        }
        __syncthreads();

        #pragma unroll
        for (int kk = 0; kk < BK; kk += 16) {
            uint32_t ah[4][4], al[4][4];
            #pragma unroll
            for (int mt = 0; mt < 4; mt++) {
                int roff = (wm * 64 + mt * 16 + a_row) * LDS + kk + a_kh;
                ldsm_x4(ah[mt], smb[0] + roff * 2);
                ldsm_x4(al[mt], smb[1] + roff * 2);
            }
            uint32_t bh[4][2], bl[4][2];
            #pragma unroll
            for (int nt = 0; nt < 4; nt++) {
                int roff = (wn * 32 + nt * 8 + b_row) * LDS + kk + b_kh;
                ldsm_x2(bh[nt], smb[2] + roff * 2);
                ldsm_x2(bl[nt], smb[3] + roff * 2);
            }
            #pragma unroll
            for (int mt = 0; mt < 4; mt++)
                #pragma unroll
                for (int nt = 0; nt < 4; nt++) {
                    mma_bf16(acc[mt][nt], ah[mt], bh[nt]);
                    mma_bf16(acc[mt][nt], ah[mt], bl[nt]);
                    mma_bf16(acc[mt][nt], al[mt], bh[nt]);
                }
        }
    }

    // epilogue -> bf16 hi/lo
    const int em = lane >> 2, en = (lane & 3) * 2;
    #pragma unroll
    for (int mt = 0; mt < 4; mt++) {
        #pragma unroll
        for (int nt = 0; nt < 4; nt++) {
            int mg0 = m0 + wm * 64 + mt * 16 + em;
            int ng  = n0 + wn * 32 + nt * 8 + en;
            int h = ng >> 6, hd = ng & 63;
            #pragma unroll
            for (int half = 0; half < 2; half++) {
                int mg = mg0 + half * 8;
                int b = mg >> 10, s = mg & 1023;
                int bhI = b * NH + h;
                float c0 = acc[mt][nt][half * 2 + 0];
                float c1 = acc[mt][nt][half * 2 + 1];
                __nv_bfloat16 h0 = __float2bfloat16(c0);
                __nv_bfloat16 h1 = __float2bfloat16(c1);
                __nv_bfloat16 l0 = __float2bfloat16(c0 - __bfloat162float(h0));
                __nv_bfloat16 l1 = __float2bfloat16(c1 - __bfloat162float(h1));
                if (z == 2) {
                    size_t base = ((size_t)bhI * HD + hd) * SEQ + s;
                    g_vth[base] = h0; g_vth[base + SEQ] = h1;
                    g_vtl[base] = l0; g_vtl[base + SEQ] = l1;
                } else {
                    size_t off = ((size_t)bhI * SEQ + s) * HD + hd;
                    __nv_bfloat16* dh = (z ? g_kh : g_qh) + off;
                    __nv_bfloat16* dl = (z ? g_kl : g_ql) + off;
                    *(uint32_t*)dh = pack_bf16(h0, h1);
                    *(uint32_t*)dl = pack_bf16(l0, l1);
                }
            }
        }
    }
}

// ---------------------------------------------------------------------------
// Attention via mma.sync, split-bf16, poly-exp softmax.
//   Block: 128 q-rows x one (b,h). 8 warps, warp tile = 16 rows x full width.
//   Loop over 16 key tiles of 64. smem: K hi/lo [64][72], V^T hi/lo [64][72].
//   Q frags held in registers for the whole kernel.
// ---------------------------------------------------------------------------
#define ATS 72                 // smem row stride (elems)
#define SM_K  (64 * ATS)       // 4608 elems per tile region

__global__ __launch_bounds__(256, 1) void attn_mma_kernel(
    const float* __restrict__ mask, float* __restrict__ out)
{
    __shared__ __nv_bfloat16 smf[4 * SM_K];

    const int tid = threadIdx.x, w = tid >> 5, lane = tid & 31;
    const int qt = blockIdx.x, bh = blockIdx.y;
    const int b = bh >> 4, h = bh & 15;
    const uint32_t smb = smem_u32(smf);
    const int gr = lane >> 2, gc2 = (lane & 3) * 2;

    // ---- load Q tile (128x64 hi/lo) into smem, then to registers ----
    {
        const __nv_bfloat16* Qh = g_qh + ((size_t)bh * SEQ + qt * 128) * HD;
        const __nv_bfloat16* Ql = g_ql + ((size_t)bh * SEQ + qt * 128) * HD;
        for (int i = tid; i < 1024; i += 256) {
            int r = i >> 3, c8 = (i & 7) * 8;
            *(uint4*)&smf[r * ATS + c8] = *(const uint4*)&Qh[r * HD + c8];
            *(uint4*)&smf[2 * SM_K + r * ATS + c8] = *(const uint4*)&Ql[r * HD + c8];
        }
    }
    __syncthreads();
    uint32_t qh[4][4], ql[4][4];
    {
        const int ar = w * 16 + (lane & 15);
        const int ac = ((lane >> 4) & 1) * 8;
        #pragma unroll
        for (int ks = 0; ks < 4; ks++) {
            ldsm_x4(qh[ks], smb + (ar * ATS + ks * 16 + ac) * 2);
            ldsm_x4(ql[ks], smb + (2 * SM_K + ar * ATS + ks * 16 + ac) * 2);
        }
    }

    float ctx[8][4] = {};
    float rs0 = 0.f, rs1 = 0.f;

    const __nv_bfloat16* Kh = g_kh + (size_t)bh * SEQ * HD;
    const __nv_bfloat16* Kl = g_kl + (size_t)bh * SEQ * HD;
    const __nv_bfloat16* Vh = g_vth + (size_t)bh * HD * SEQ;
    const __nv_bfloat16* Vl = g_vtl + (size_t)bh * HD * SEQ;
    const float* Mb = mask + (size_t)b * SEQ * SEQ
                      + (size_t)(qt * 128 + w * 16 + gr) * SEQ + gc2;

    const int br = (lane & 7) + ((lane >> 4) << 3);  // B-frag row within 16-pair
    const int bc = ((lane >> 3) & 1) * 8;            // B-frag k-half

    for (int kt = 0; kt < 16; kt++) {
        __syncthreads();
        for (int i = tid; i < 512; i += 256) {
            int r = i >> 3, c8 = (i & 7) * 8;
            *(uint4*)&smf[r * ATS + c8] =
                *(const uint4*)&Kh[(size_t)(kt * 64 + r) * HD + c8];
            *(uint4*)&smf[SM_K + r * ATS + c8] =
                *(const uint4*)&Kl[(size_t)(kt * 64 + r) * HD + c8];
            *(uint4*)&smf[2 * SM_K + r * ATS + c8] =
                *(const uint4*)&Vh[(size_t)r * SEQ + kt * 64 + c8];
            *(uint4*)&smf[3 * SM_K + r * ATS + c8] =
                *(const uint4*)&Vl[(size_t)r * SEQ + kt * 64 + c8];
        }
        __syncthreads();

        // ---- scores = Q K^T (split-bf16, 3 MMAs) ----
        float acc[8][4] = {};
        #pragma unroll
        for (int ks = 0; ks < 4; ks++) {
            #pragma unroll
            for (int ntp = 0; ntp < 4; ntp++) {
                uint32_t kh4[4], kl4[4];
                int off = ((ntp * 16 + br) * ATS + ks * 16 + bc) * 2;
                ldsm_x4(kh4, smb + off);
                ldsm_x4(kl4, smb + SM_K * 2 + off);
                mma_bf16(acc[ntp * 2],     qh[ks], &kh4[0]);
                mma_bf16(acc[ntp * 2],     qh[ks], &kl4[0]);
                mma_bf16(acc[ntp * 2],     ql[ks], &kh4[0]);
                mma_bf16(acc[ntp * 2 + 1], qh[ks], &kh4[2]);
                mma_bf16(acc[ntp * 2 + 1], qh[ks], &kl4[2]);
                mma_bf16(acc[ntp * 2 + 1], ql[ks], &kh4[2]);
            }
        }

        // ---- e = poly_exp(s/8) * mask; row sums; build P frags ----
        uint32_t ph[4][4], pl[4][4];
        const float* Mk = Mb + kt * 64;
        #pragma unroll
        for (int nt = 0; nt < 8; nt++) {
            float2 m0 = *(const float2*)&Mk[nt * 8];
            float2 m1 = *(const float2*)&Mk[8 * SEQ + nt * 8];
            float e0 = fexp8(acc[nt][0]) * m0.x;
            float e1 = fexp8(acc[nt][1]) * m0.y;
            float e2 = fexp8(acc[nt][2]) * m1.x;
            float e3 = fexp8(acc[nt][3]) * m1.y;
            rs0 += e0 + e1;
            rs1 += e2 + e3;
            __nv_bfloat16 h0 = __float2bfloat16(e0), h1 = __float2bfloat16(e1);
            __nv_bfloat16 h2 = __float2bfloat16(e2), h3 = __float2bfloat16(e3);
            __nv_bfloat16 l0 = __float2bfloat16(e0 - __bfloat162float(h0));
            __nv_bfloat16 l1 = __float2bfloat16(e1 - __bfloat162float(h1));
            __nv_bfloat16 l2 = __float2bfloat16(e2 - __bfloat162float(h2));
            __nv_bfloat16 l3 = __float2bfloat16(e3 - __bfloat162float(h3));
            int u = nt >> 1, sel = (nt & 1) * 2;
            ph[u][sel]     = pack_bf16(h0, h1);
            ph[u][sel + 1] = pack_bf16(h2, h3);
            pl[u][sel]     = pack_bf16(l0, l1);
            pl[u][sel + 1] = pack_bf16(l2, l3);
        }

        // ---- ctx += P V (split-bf16, 3 MMAs) ----
        #pragma unroll
        for (int u = 0; u < 4; u++) {
            #pragma unroll
            for (int dtp = 0; dtp < 4; dtp++) {
                uint32_t vh4[4], vl4[4];
                int off = ((dtp * 16 + br) * ATS + u * 16 + bc) * 2;
                ldsm_x4(vh4, smb + 2 * SM_K * 2 + off);
                ldsm_x4(vl4, smb + 3 * SM_K * 2 + off);
                mma_bf16(ctx[dtp * 2],     ph[u], &vh4[0]);
                mma_bf16(ctx[dtp * 2],     ph[u], &vl4[0]);
                mma_bf16(ctx[dtp * 2],     pl[u], &vh4[0]);
                mma_bf16(ctx[dtp * 2 + 1], ph[u], &vh4[2]);
                mma_bf16(ctx[dtp * 2 + 1], ph[u], &vl4[2]);
                mma_bf16(ctx[dtp * 2 + 1], pl[u], &vh4[2]);
            }
        }
    }

    // ---- denominators + output ----
    rs0 += __shfl_xor_sync(0xffffffffu, rs0, 1);
    rs0 += __shfl_xor_sync(0xffffffffu, rs0, 2);
    rs1 += __shfl_xor_sync(0xffffffffu, rs1, 1);
    rs1 += __shfl_xor_sync(0xffffffffu, rs1, 2);
    float inv0 = 1.0f / (rs0 + 1e-8f);
    float inv1 = 1.0f / (rs1 + 1e-8f);

    const int s0 = qt * 128 + w * 16 + gr;
    float* O = out + (((size_t)b * SEQ + s0) * NH + h) * HD + gc2;
    #pragma unroll
    for (int dt = 0; dt < 8; dt++) {
        *(float2*)&O[dt * 8] =
            make_float2(ctx[dt][0] * inv0, ctx[dt][1] * inv0);
        *(float2*)&O[(size_t)8 * NH * HD + dt * 8] =
            make_float2(ctx[dt][2] * inv1, ctx[dt][3] * inv1);
    }
}

// ---------------------------------------------------------------------------
extern "C" void kernel_launch(void* const* d_in, const int* in_sizes, int n_in,
                              void* d_out, int out_size)
{
    const float* x    = (const float*)d_in[0];
    const float* mask = (const float*)d_in[1];
    const float* Wq   = (const float*)d_in[2];
    const float* Wk   = (const float*)d_in[3];
    const float* Wv   = (const float*)d_in[4];
    float* out = (float*)d_out;

    convert_x_kernel<<<BATCH * SEQ, 256>>>(x);
    convert_wt_kernel<<<dim3(32, 32, 3), dim3(32, 8)>>>(Wq, Wk, Wv);
    qkv_mma_kernel<<<dim3(64, 8, 3), 256>>>();
    attn_mma_kernel<<<dim3(8, 128), 256>>>(mask, out);
}

// round 6
// speedup vs baseline: 2.7825x; 1.3086x over previous
#include <cuda_runtime.h>
#include <cuda_bf16.h>
#include <cstdint>

#define BATCH 8
#define SEQ   1024
#define DIM   1024
#define NH    16
#define HD    64

// split-bf16 operands for MMA projections
__device__ __nv_bfloat16 g_xh[BATCH*SEQ*DIM];     // x hi   [m][k]
__device__ __nv_bfloat16 g_xl[BATCH*SEQ*DIM];     // x lo
__device__ __nv_bfloat16 g_wth[3*DIM*DIM];        // W^T hi [n][k]
__device__ __nv_bfloat16 g_wtl[3*DIM*DIM];        // W^T lo

// attention operands (written by QKV GEMM epilogue)
__device__ __nv_bfloat16 g_qh [BATCH*NH*SEQ*HD];  // Q hi  [bh][s][hd]
__device__ __nv_bfloat16 g_ql [BATCH*NH*SEQ*HD];
__device__ __nv_bfloat16 g_kh [BATCH*NH*SEQ*HD];  // K hi  [bh][s][hd]
__device__ __nv_bfloat16 g_kl [BATCH*NH*SEQ*HD];
__device__ __nv_bfloat16 g_vth[BATCH*NH*HD*SEQ];  // V^T hi [bh][hd][s]
__device__ __nv_bfloat16 g_vtl[BATCH*NH*HD*SEQ];

// ---------------------------------------------------------------------------
// helpers
// ---------------------------------------------------------------------------
__device__ __forceinline__ uint32_t smem_u32(const void* p) {
    uint32_t a;
    asm("{ .reg .u64 t; cvta.to.shared.u64 t, %1; cvt.u32.u64 %0, t; }"
        : "=r"(a) : "l"(p));
    return a;
}
__device__ __forceinline__ void ldsm_x4(uint32_t a[4], uint32_t addr) {
    asm volatile("ldmatrix.sync.aligned.m8n8.x4.shared.b16 {%0,%1,%2,%3}, [%4];"
                 : "=r"(a[0]), "=r"(a[1]), "=r"(a[2]), "=r"(a[3]) : "r"(addr));
}
__device__ __forceinline__ void ldsm_x2(uint32_t b[2], uint32_t addr) {
    asm volatile("ldmatrix.sync.aligned.m8n8.x2.shared.b16 {%0,%1}, [%2];"
                 : "=r"(b[0]), "=r"(b[1]) : "r"(addr));
}
__device__ __forceinline__ void mma_bf16(float c[4], const uint32_t a[4],
                                         const uint32_t b[2]) {
    asm volatile(
        "mma.sync.aligned.m16n8k16.row.col.f32.bf16.bf16.f32 "
        "{%0,%1,%2,%3}, {%4,%5,%6,%7}, {%8,%9}, {%0,%1,%2,%3};"
        : "+f"(c[0]), "+f"(c[1]), "+f"(c[2]), "+f"(c[3])
        : "r"(a[0]), "r"(a[1]), "r"(a[2]), "r"(a[3]), "r"(b[0]), "r"(b[1]));
}
__device__ __forceinline__ uint32_t pack_bf16(__nv_bfloat16 a, __nv_bfloat16 b) {
    __nv_bfloat162 p; p.x = a; p.y = b;
    return *(uint32_t*)&p;
}
__device__ __forceinline__ void cp16(uint32_t dst, const void* src) {
    asm volatile("cp.async.cg.shared.global [%0], [%1], 16;"
                 :: "r"(dst), "l"(src));
}
#define CP_COMMIT() asm volatile("cp.async.commit_group;" ::: "memory")
#define CP_WAIT(n)  asm volatile("cp.async.wait_group %0;" :: "n"(n) : "memory")

// exp(s/8) via exp2 poly: t = s*log2e/8; magic round; degree-5 Taylor on [-.5,.5]
__device__ __forceinline__ float fexp8(float s) {
    float t = s * 0.18033688011112042f;          // log2(e)/8
    float k = t + 12582912.0f;                   // 1.5*2^23 magic round
    float j = k - 12582912.0f;
    float f = t - j;
    float p = 1.3333558147e-3f;
    p = fmaf(p, f, 9.6181291076e-3f);
    p = fmaf(p, f, 5.5504108665e-2f);
    p = fmaf(p, f, 2.4022650696e-1f);
    p = fmaf(p, f, 6.9314718056e-1f);
    p = fmaf(p, f, 1.0f);
    int ib = __float_as_int(k) - 0x4B400000;
    float scale = __int_as_float((ib + 127) << 23);
    return p * scale;
}

// ---------------------------------------------------------------------------
// Preprocess: split x -> (hi, lo) bf16
// ---------------------------------------------------------------------------
__global__ __launch_bounds__(256) void convert_x_kernel(const float* __restrict__ x) {
    int i = (blockIdx.x * 256 + threadIdx.x) * 4;
    float4 v = *(const float4*)(x + i);
    __nv_bfloat16 h0 = __float2bfloat16(v.x), h1 = __float2bfloat16(v.y);
    __nv_bfloat16 h2 = __float2bfloat16(v.z), h3 = __float2bfloat16(v.w);
    __nv_bfloat162 hi01, hi23, lo01, lo23;
    hi01.x = h0; hi01.y = h1; hi23.x = h2; hi23.y = h3;
    lo01.x = __float2bfloat16(v.x - __bfloat162float(h0));
    lo01.y = __float2bfloat16(v.y - __bfloat162float(h1));
    lo23.x = __float2bfloat16(v.z - __bfloat162float(h2));
    lo23.y = __float2bfloat16(v.w - __bfloat162float(h3));
    *(__nv_bfloat162*)(g_xh + i)     = hi01;
    *(__nv_bfloat162*)(g_xh + i + 2) = hi23;
    *(__nv_bfloat162*)(g_xl + i)     = lo01;
    *(__nv_bfloat162*)(g_xl + i + 2) = lo23;
}

// Preprocess: W[k][n] -> Wt[n][k] split into (hi, lo) bf16
__global__ __launch_bounds__(256) void convert_wt_kernel(
    const float* __restrict__ Wq, const float* __restrict__ Wk,
    const float* __restrict__ Wv)
{
    __shared__ float t[32][33];
    const int z = blockIdx.z;
    const float* __restrict__ W = (z == 0) ? Wq : (z == 1 ? Wk : Wv);
    const int n0 = blockIdx.x * 32, k0 = blockIdx.y * 32;
    const int tx = threadIdx.x, ty = threadIdx.y;   // block (32, 8)

    #pragma unroll
    for (int i = ty; i < 32; i += 8)
        t[i][tx] = W[(size_t)(k0 + i) * DIM + n0 + tx];
    __syncthreads();

    __nv_bfloat16* wh = g_wth + (size_t)z * DIM * DIM;
    __nv_bfloat16* wl = g_wtl + (size_t)z * DIM * DIM;
    #pragma unroll
    for (int i = ty; i < 32; i += 8) {
        float v = t[tx][i];
        __nv_bfloat16 h = __float2bfloat16(v);
        wh[(size_t)(n0 + i) * DIM + k0 + tx] = h;
        wl[(size_t)(n0 + i) * DIM + k0 + tx] = __float2bfloat16(v - __bfloat162float(h));
    }
}

// ---------------------------------------------------------------------------
// QKV projection GEMM, cp.async double-buffered.
//   128x128 tile, 8 warps (2x4), warp tile 64x32, BK=32.
//   smem (dynamic): 2 bufs x 4 regions x 128 x LDS bf16 = 81920 B.
// ---------------------------------------------------------------------------
#define BK 32
#define LDS 40
#define QREG (128 * LDS)          // 5120 elems per region
#define QBUF (4 * QREG)           // 20480 elems per buffer
#define QKV_SMEM (2 * QBUF * 2)   // bytes

__device__ __forceinline__ void qkv_cp_blk(
    uint32_t dstb, const __nv_bfloat16* const* srcs, int k0, int tid)
{
    #pragma unroll
    for (int t = 0; t < 4; t++) {
        const __nv_bfloat16* s = srcs[t] + k0;
        #pragma unroll
        for (int i = tid; i < 512; i += 256) {
            int r = i >> 2, c8 = (i & 3) * 8;
            cp16(dstb + (t * QREG + r * LDS + c8) * 2,
                 s + (size_t)r * DIM + c8);
        }
    }
}

__global__ __launch_bounds__(256) void qkv_mma_kernel()
{
    extern __shared__ __nv_bfloat16 smd[];
    const uint32_t smb = smem_u32(smd);

    const int tid  = threadIdx.x;
    const int w    = tid >> 5, lane = tid & 31;
    const int wm   = w >> 2, wn = w & 3;
    const int m0   = blockIdx.x * 128;
    const int n0   = blockIdx.y * 128;
    const int z    = blockIdx.z;

    const __nv_bfloat16* srcs[4] = {
        g_xh + (size_t)m0 * DIM,
        g_xl + (size_t)m0 * DIM,
        g_wth + (size_t)z * DIM * DIM + (size_t)n0 * DIM,
        g_wtl + (size_t)z * DIM * DIM + (size_t)n0 * DIM
    };

    const int a_row = lane & 15, a_kh = (lane >> 4) * 8;
    const int b_row = lane & 7,  b_kh = ((lane >> 3) & 1) * 8;

    float acc[4][4][4] = {};

    qkv_cp_blk(smb, srcs, 0, tid);             CP_COMMIT();
    qkv_cp_blk(smb + QBUF * 2, srcs, BK, tid); CP_COMMIT();

    const int NB = DIM / BK;   // 32
    for (int blk = 0; blk < NB; blk++) {
        if (blk == NB - 1) CP_WAIT(0); else CP_WAIT(1);
        __syncthreads();

        const uint32_t bb = smb + (blk & 1) * QBUF * 2;
        #pragma unroll
        for (int kk = 0; kk < BK; kk += 16) {
            uint32_t ah[4][4], al[4][4];
            #pragma unroll
            for (int mt = 0; mt < 4; mt++) {
                int roff = ((wm * 64 + mt * 16 + a_row) * LDS + kk + a_kh) * 2;
                ldsm_x4(ah[mt], bb + roff);
                ldsm_x4(al[mt], bb + QREG * 2 + roff);
            }
            uint32_t bh[4][2], bl[4][2];
            #pragma unroll
            for (int nt = 0; nt < 4; nt++) {
                int roff = ((wn * 32 + nt * 8 + b_row) * LDS + kk + b_kh) * 2;
                ldsm_x2(bh[nt], bb + 2 * QREG * 2 + roff);
                ldsm_x2(bl[nt], bb + 3 * QREG * 2 + roff);
            }
            #pragma unroll
            for (int mt = 0; mt < 4; mt++)
                #pragma unroll
                for (int nt = 0; nt < 4; nt++) {
                    mma_bf16(acc[mt][nt], ah[mt], bh[nt]);
                    mma_bf16(acc[mt][nt], ah[mt], bl[nt]);
                    mma_bf16(acc[mt][nt], al[mt], bh[nt]);
                }
        }
        __syncthreads();
        if (blk + 2 < NB) {
            qkv_cp_blk(smb + (blk & 1) * QBUF * 2, srcs, (blk + 2) * BK, tid);
            CP_COMMIT();
        }
    }

    // epilogue -> bf16 hi/lo
    const int em = lane >> 2, en = (lane & 3) * 2;
    #pragma unroll
    for (int mt = 0; mt < 4; mt++) {
        #pragma unroll
        for (int nt = 0; nt < 4; nt++) {
            int mg0 = m0 + wm * 64 + mt * 16 + em;
            int ng  = n0 + wn * 32 + nt * 8 + en;
            int h = ng >> 6, hd = ng & 63;
            #pragma unroll
            for (int half = 0; half < 2; half++) {
                int mg = mg0 + half * 8;
                int b = mg >> 10, s = mg & 1023;
                int bhI = b * NH + h;
                float c0 = acc[mt][nt][half * 2 + 0];
                float c1 = acc[mt][nt][half * 2 + 1];
                __nv_bfloat16 h0 = __float2bfloat16(c0);
                __nv_bfloat16 h1 = __float2bfloat16(c1);
                __nv_bfloat16 l0 = __float2bfloat16(c0 - __bfloat162float(h0));
                __nv_bfloat16 l1 = __float2bfloat16(c1 - __bfloat162float(h1));
                if (z == 2) {
                    size_t base = ((size_t)bhI * HD + hd) * SEQ + s;
                    g_vth[base] = h0; g_vth[base + SEQ] = h1;
                    g_vtl[base] = l0; g_vtl[base + SEQ] = l1;
                } else {
                    size_t off = ((size_t)bhI * SEQ + s) * HD + hd;
                    __nv_bfloat16* dh = (z ? g_kh : g_qh) + off;
                    __nv_bfloat16* dl = (z ? g_kl : g_ql) + off;
                    *(uint32_t*)dh = pack_bf16(h0, h1);
                    *(uint32_t*)dl = pack_bf16(l0, l1);
                }
            }
        }
    }
}

// ---------------------------------------------------------------------------
// Attention via mma.sync, split-bf16, poly-exp softmax, cp.async pipelined.
//   128 q-rows x one (b,h), 8 warps. smem (dynamic):
//   Qh/Ql [128][ATS] + 2 bufs x (Kh,Kl,Vh,Vl)[64][ATS] = 110592 B.
// ---------------------------------------------------------------------------
#define ATS 72
#define SM_K  (64 * ATS)          // 4608 elems per region
#define AQ_REG (128 * ATS)        // 9216 elems per Q region
#define ABUF0 (2 * AQ_REG)        // elem offset of kv buf 0
#define ABUF  (4 * SM_K)          // elems per kv buffer
#define ATTN_SMEM ((ABUF0 + 2 * ABUF) * 2)

__device__ __forceinline__ void attn_cp_tile(
    uint32_t dstb, const __nv_bfloat16* Kh, const __nv_bfloat16* Kl,
    const __nv_bfloat16* Vh, const __nv_bfloat16* Vl, int kt, int tid)
{
    #pragma unroll
    for (int i = tid; i < 512; i += 256) {
        int r = i >> 3, c8 = (i & 7) * 8;
        uint32_t d = dstb + (r * ATS + c8) * 2;
        cp16(d,                Kh + (size_t)(kt * 64 + r) * HD + c8);
        cp16(d + SM_K * 2,     Kl + (size_t)(kt * 64 + r) * HD + c8);
        cp16(d + 2 * SM_K * 2, Vh + (size_t)r * SEQ + kt * 64 + c8);
        cp16(d + 3 * SM_K * 2, Vl + (size_t)r * SEQ + kt * 64 + c8);
    }
}

__global__ __launch_bounds__(256) void attn_mma_kernel(
    const float* __restrict__ mask, float* __restrict__ out)
{
    extern __shared__ __nv_bfloat16 smd[];
    const uint32_t smb = smem_u32(smd);

    const int tid = threadIdx.x, w = tid >> 5, lane = tid & 31;
    const int qt = blockIdx.x, bh = blockIdx.y;
    const int b = bh >> 4, h = bh & 15;
    const int gr = lane >> 2, gc2 = (lane & 3) * 2;

    const __nv_bfloat16* Qh = g_qh + ((size_t)bh * SEQ + qt * 128) * HD;
    const __nv_bfloat16* Ql = g_ql + ((size_t)bh * SEQ + qt * 128) * HD;
    const __nv_bfloat16* Kh = g_kh + (size_t)bh * SEQ * HD;
    const __nv_bfloat16* Kl = g_kl + (size_t)bh * SEQ * HD;
    const __nv_bfloat16* Vh = g_vth + (size_t)bh * HD * SEQ;
    const __nv_bfloat16* Vl = g_vtl + (size_t)bh * HD * SEQ;

    // group 0: Q tiles
    #pragma unroll
    for (int i = tid; i < 1024; i += 256) {
        int r = i >> 3, c8 = (i & 7) * 8;
        cp16(smb + (r * ATS + c8) * 2,            Qh + (size_t)r * HD + c8);
        cp16(smb + (AQ_REG + r * ATS + c8) * 2,   Ql + (size_t)r * HD + c8);
    }
    CP_COMMIT();
    attn_cp_tile(smb + ABUF0 * 2,            Kh, Kl, Vh, Vl, 0, tid); CP_COMMIT();
    attn_cp_tile(smb + (ABUF0 + ABUF) * 2,   Kh, Kl, Vh, Vl, 1, tid); CP_COMMIT();

    CP_WAIT(2);              // Q ready
    __syncthreads();

    uint32_t qh[4][4], ql[4][4];
    {
        const int ar = w * 16 + (lane & 15);
        const int ac = ((lane >> 4) & 1) * 8;
        #pragma unroll
        for (int ks = 0; ks < 4; ks++) {
            ldsm_x4(qh[ks], smb + (ar * ATS + ks * 16 + ac) * 2);
            ldsm_x4(ql[ks], smb + (AQ_REG + ar * ATS + ks * 16 + ac) * 2);
        }
    }

    float ctx[8][4] = {};
    float rs0 = 0.f, rs1 = 0.f;

    const float* Mb = mask + (size_t)b * SEQ * SEQ
                      + (size_t)(qt * 128 + w * 16 + gr) * SEQ + gc2;

    const int br = (lane & 7) + ((lane >> 4) << 3);
    const int bc = ((lane >> 3) & 1) * 8;

    for (int kt = 0; kt < 16; kt++) {
        if (kt == 15) CP_WAIT(0); else CP_WAIT(1);
        __syncthreads();

        const uint32_t bb = smb + (ABUF0 + (kt & 1) * ABUF) * 2;

        // ---- scores = Q K^T (split-bf16, 3 MMAs) ----
        float acc[8][4] = {};
        #pragma unroll
        for (int ks = 0; ks < 4; ks++) {
            #pragma unroll
            for (int ntp = 0; ntp < 4; ntp++) {
                uint32_t kh4[4], kl4[4];
                int off = ((ntp * 16 + br) * ATS + ks * 16 + bc) * 2;
                ldsm_x4(kh4, bb + off);
                ldsm_x4(kl4, bb + SM_K * 2 + off);
                mma_bf16(acc[ntp * 2],     qh[ks], &kh4[0]);
                mma_bf16(acc[ntp * 2],     qh[ks], &kl4[0]);
                mma_bf16(acc[ntp * 2],     ql[ks], &kh4[0]);
                mma_bf16(acc[ntp * 2 + 1], qh[ks], &kh4[2]);
                mma_bf16(acc[ntp * 2 + 1], qh[ks], &kl4[2]);
                mma_bf16(acc[ntp * 2 + 1], ql[ks], &kh4[2]);
            }
        }

        // ---- e = poly_exp(s/8) * mask; row sums; build P frags ----
        uint32_t ph[4][4], pl[4][4];
        const float* Mk = Mb + kt * 64;
        #pragma unroll
        for (int nt = 0; nt < 8; nt++) {
            float2 m0 = *(const float2*)&Mk[nt * 8];
            float2 m1 = *(const float2*)&Mk[8 * SEQ + nt * 8];
            float e0 = fexp8(acc[nt][0]) * m0.x;
            float e1 = fexp8(acc[nt][1]) * m0.y;
            float e2 = fexp8(acc[nt][2]) * m1.x;
            float e3 = fexp8(acc[nt][3]) * m1.y;
            rs0 += e0 + e1;
            rs1 += e2 + e3;
            __nv_bfloat16 h0 = __float2bfloat16(e0), h1 = __float2bfloat16(e1);
            __nv_bfloat16 h2 = __float2bfloat16(e2), h3 = __float2bfloat16(e3);
            __nv_bfloat16 l0 = __float2bfloat16(e0 - __bfloat162float(h0));
            __nv_bfloat16 l1 = __float2bfloat16(e1 - __bfloat162float(h1));
            __nv_bfloat16 l2 = __float2bfloat16(e2 - __bfloat162float(h2));
            __nv_bfloat16 l3 = __float2bfloat16(e3 - __bfloat162float(h3));
            int u = nt >> 1, sel = (nt & 1) * 2;
            ph[u][sel]     = pack_bf16(h0, h1);
            ph[u][sel + 1] = pack_bf16(h2, h3);
            pl[u][sel]     = pack_bf16(l0, l1);
            pl[u][sel + 1] = pack_bf16(l2, l3);
        }

        // ---- ctx += P V (split-bf16, 3 MMAs) ----
        #pragma unroll
        for (int u = 0; u < 4; u++) {
            #pragma unroll
            for (int dtp = 0; dtp < 4; dtp++) {
                uint32_t vh4[4], vl4[4];
                int off = ((dtp * 16 + br) * ATS + u * 16 + bc) * 2;
                ldsm_x4(vh4, bb + 2 * SM_K * 2 + off);
                ldsm_x4(vl4, bb + 3 * SM_K * 2 + off);
                mma_bf16(ctx[dtp * 2],     ph[u], &vh4[0]);
                mma_bf16(ctx[dtp * 2],     ph[u], &vl4[0]);
                mma_bf16(ctx[dtp * 2],     pl[u], &vh4[0]);
                mma_bf16(ctx[dtp * 2 + 1], ph[u], &vh4[2]);
                mma_bf16(ctx[dtp * 2 + 1], ph[u], &vl4[2]);
                mma_bf16(ctx[dtp * 2 + 1], pl[u], &vh4[2]);
            }
        }

        __syncthreads();
        if (kt + 2 < 16) {
            attn_cp_tile(smb + (ABUF0 + (kt & 1) * ABUF) * 2,
                         Kh, Kl, Vh, Vl, kt + 2, tid);
            CP_COMMIT();
        }
    }

    // ---- denominators + output ----
    rs0 += __shfl_xor_sync(0xffffffffu, rs0, 1);
    rs0 += __shfl_xor_sync(0xffffffffu, rs0, 2);
    rs1 += __shfl_xor_sync(0xffffffffu, rs1, 1);
    rs1 += __shfl_xor_sync(0xffffffffu, rs1, 2);
    float inv0 = 1.0f / (rs0 + 1e-8f);
    float inv1 = 1.0f / (rs1 + 1e-8f);

    const int s0 = qt * 128 + w * 16 + gr;
    float* O = out + (((size_t)b * SEQ + s0) * NH + h) * HD + gc2;
    #pragma unroll
    for (int dt = 0; dt < 8; dt++) {
        *(float2*)&O[dt * 8] =
            make_float2(ctx[dt][0] * inv0, ctx[dt][1] * inv0);
        *(float2*)&O[(size_t)8 * NH * HD + dt * 8] =
            make_float2(ctx[dt][2] * inv1, ctx[dt][3] * inv1);
    }
}

// ---------------------------------------------------------------------------
extern "C" void kernel_launch(void* const* d_in, const int* in_sizes, int n_in,
                              void* d_out, int out_size)
{
    const float* x    = (const float*)d_in[0];
    const float* mask = (const float*)d_in[1];
    const float* Wq   = (const float*)d_in[2];
    const float* Wk   = (const float*)d_in[3];
    const float* Wv   = (const float*)d_in[4];
    float* out = (float*)d_out;

    static int init = 0;
    if (!init) {
        cudaFuncSetAttribute(qkv_mma_kernel,
            cudaFuncAttributeMaxDynamicSharedMemorySize, QKV_SMEM);
        cudaFuncSetAttribute(attn_mma_kernel,
            cudaFuncAttributeMaxDynamicSharedMemorySize, ATTN_SMEM);
        init = 1;
    }

    convert_x_kernel<<<BATCH * SEQ, 256>>>(x);
    convert_wt_kernel<<<dim3(32, 32, 3), dim3(32, 8)>>>(Wq, Wk, Wv);
    qkv_mma_kernel<<<dim3(64, 8, 3), 256, QKV_SMEM>>>();
    attn_mma_kernel<<<dim3(8, 128), 256, ATTN_SMEM>>>(mask, out);
}

// round 7
// speedup vs baseline: 2.8632x; 1.0290x over previous
#include <cuda_runtime.h>
#include <cuda_bf16.h>
#include <cstdint>

#define BATCH 8
#define SEQ   1024
#define DIM   1024
#define NH    16
#define HD    64

// split-bf16 operands for MMA projections
__device__ __nv_bfloat16 g_xh[BATCH*SEQ*DIM];     // x hi   [m][k]
__device__ __nv_bfloat16 g_xl[BATCH*SEQ*DIM];     // x lo
__device__ __nv_bfloat16 g_wth[3*DIM*DIM];        // W^T hi [n][k]
__device__ __nv_bfloat16 g_wtl[3*DIM*DIM];        // W^T lo

// attention operands (written by QKV GEMM epilogue)
__device__ __nv_bfloat16 g_qh [BATCH*NH*SEQ*HD];  // Q hi  [bh][s][hd]
__device__ __nv_bfloat16 g_ql [BATCH*NH*SEQ*HD];
__device__ __nv_bfloat16 g_kh [BATCH*NH*SEQ*HD];  // K hi  [bh][s][hd]
__device__ __nv_bfloat16 g_kl [BATCH*NH*SEQ*HD];
__device__ __nv_bfloat16 g_vth[BATCH*NH*HD*SEQ];  // V^T hi [bh][hd][s]
__device__ __nv_bfloat16 g_vtl[BATCH*NH*HD*SEQ];

// ---------------------------------------------------------------------------
// helpers
// ---------------------------------------------------------------------------
__device__ __forceinline__ uint32_t smem_u32(const void* p) {
    uint32_t a;
    asm("{ .reg .u64 t; cvta.to.shared.u64 t, %1; cvt.u32.u64 %0, t; }"
        : "=r"(a) : "l"(p));
    return a;
}
__device__ __forceinline__ void ldsm_x4(uint32_t a[4], uint32_t addr) {
    asm volatile("ldmatrix.sync.aligned.m8n8.x4.shared.b16 {%0,%1,%2,%3}, [%4];"
                 : "=r"(a[0]), "=r"(a[1]), "=r"(a[2]), "=r"(a[3]) : "r"(addr));
}
__device__ __forceinline__ void ldsm_x2(uint32_t b[2], uint32_t addr) {
    asm volatile("ldmatrix.sync.aligned.m8n8.x2.shared.b16 {%0,%1}, [%2];"
                 : "=r"(b[0]), "=r"(b[1]) : "r"(addr));
}
__device__ __forceinline__ void mma_bf16(float c[4], const uint32_t a[4],
                                         const uint32_t b[2]) {
    asm volatile(
        "mma.sync.aligned.m16n8k16.row.col.f32.bf16.bf16.f32 "
        "{%0,%1,%2,%3}, {%4,%5,%6,%7}, {%8,%9}, {%0,%1,%2,%3};"
        : "+f"(c[0]), "+f"(c[1]), "+f"(c[2]), "+f"(c[3])
        : "r"(a[0]), "r"(a[1]), "r"(a[2]), "r"(a[3]), "r"(b[0]), "r"(b[1]));
}
__device__ __forceinline__ uint32_t pack_bf16(__nv_bfloat16 a, __nv_bfloat16 b) {
    __nv_bfloat162 p; p.x = a; p.y = b;
    return *(uint32_t*)&p;
}
// packed {lo, hi} bf16x2 from two floats
__device__ __forceinline__ uint32_t cvt_bf16x2(float lo, float hi) {
    uint32_t r;
    asm("cvt.rn.bf16x2.f32 %0, %1, %2;" : "=r"(r) : "f"(hi), "f"(lo));
    return r;
}
__device__ __forceinline__ void cp16(uint32_t dst, const void* src) {
    asm volatile("cp.async.cg.shared.global [%0], [%1], 16;"
                 :: "r"(dst), "l"(src));
}
#define CP_COMMIT() asm volatile("cp.async.commit_group;" ::: "memory")
#define CP_WAIT(n)  asm volatile("cp.async.wait_group %0;" :: "n"(n) : "memory")

// exp(s/8) via exp2 poly: t = s*log2e/8; magic round; degree-5 Taylor on [-.5,.5]
__device__ __forceinline__ float fexp8(float s) {
    float t = s * 0.18033688011112042f;          // log2(e)/8
    float k = t + 12582912.0f;                   // 1.5*2^23 magic round
    float j = k - 12582912.0f;
    float f = t - j;
    float p = 1.3333558147e-3f;
    p = fmaf(p, f, 9.6181291076e-3f);
    p = fmaf(p, f, 5.5504108665e-2f);
    p = fmaf(p, f, 2.4022650696e-1f);
    p = fmaf(p, f, 6.9314718056e-1f);
    p = fmaf(p, f, 1.0f);
    int ib = __float_as_int(k) - 0x4B400000;
    float scale = __int_as_float((ib + 127) << 23);
    return p * scale;
}

// ---------------------------------------------------------------------------
// Preprocess: split x -> (hi, lo) bf16
// ---------------------------------------------------------------------------
__global__ __launch_bounds__(256) void convert_x_kernel(const float* __restrict__ x) {
    int i = (blockIdx.x * 256 + threadIdx.x) * 4;
    float4 v = *(const float4*)(x + i);
    __nv_bfloat16 h0 = __float2bfloat16(v.x), h1 = __float2bfloat16(v.y);
    __nv_bfloat16 h2 = __float2bfloat16(v.z), h3 = __float2bfloat16(v.w);
    __nv_bfloat162 hi01, hi23, lo01, lo23;
    hi01.x = h0; hi01.y = h1; hi23.x = h2; hi23.y = h3;
    lo01.x = __float2bfloat16(v.x - __bfloat162float(h0));
    lo01.y = __float2bfloat16(v.y - __bfloat162float(h1));
    lo23.x = __float2bfloat16(v.z - __bfloat162float(h2));
    lo23.y = __float2bfloat16(v.w - __bfloat162float(h3));
    *(__nv_bfloat162*)(g_xh + i)     = hi01;
    *(__nv_bfloat162*)(g_xh + i + 2) = hi23;
    *(__nv_bfloat162*)(g_xl + i)     = lo01;
    *(__nv_bfloat162*)(g_xl + i + 2) = lo23;
}

// Preprocess: W[k][n] -> Wt[n][k] split into (hi, lo) bf16
__global__ __launch_bounds__(256) void convert_wt_kernel(
    const float* __restrict__ Wq, const float* __restrict__ Wk,
    const float* __restrict__ Wv)
{
    __shared__ float t[32][33];
    const int z = blockIdx.z;
    const float* __restrict__ W = (z == 0) ? Wq : (z == 1 ? Wk : Wv);
    const int n0 = blockIdx.x * 32, k0 = blockIdx.y * 32;
    const int tx = threadIdx.x, ty = threadIdx.y;   // block (32, 8)

    #pragma unroll
    for (int i = ty; i < 32; i += 8)
        t[i][tx] = W[(size_t)(k0 + i) * DIM + n0 + tx];
    __syncthreads();

    __nv_bfloat16* wh = g_wth + (size_t)z * DIM * DIM;
    __nv_bfloat16* wl = g_wtl + (size_t)z * DIM * DIM;
    #pragma unroll
    for (int i = ty; i < 32; i += 8) {
        float v = t[tx][i];
        __nv_bfloat16 h = __float2bfloat16(v);
        wh[(size_t)(n0 + i) * DIM + k0 + tx] = h;
        wl[(size_t)(n0 + i) * DIM + k0 + tx] = __float2bfloat16(v - __bfloat162float(h));
    }
}

// ---------------------------------------------------------------------------
// QKV projection GEMM, cp.async distance-1 double buffer, 1 sync/iter.
// ---------------------------------------------------------------------------
#define BK 32
#define LDS 40
#define QREG (128 * LDS)          // 5120 elems per region
#define QBUF (4 * QREG)           // 20480 elems per buffer
#define QKV_SMEM (2 * QBUF * 2)   // bytes

__device__ __forceinline__ void qkv_cp_blk(
    uint32_t dstb, const __nv_bfloat16* const* srcs, int k0, int tid)
{
    #pragma unroll
    for (int t = 0; t < 4; t++) {
        const __nv_bfloat16* s = srcs[t] + k0;
        #pragma unroll
        for (int i = tid; i < 512; i += 256) {
            int r = i >> 2, c8 = (i & 3) * 8;
            cp16(dstb + (t * QREG + r * LDS + c8) * 2,
                 s + (size_t)r * DIM + c8);
        }
    }
}

__global__ __launch_bounds__(256, 2) void qkv_mma_kernel()
{
    extern __shared__ __nv_bfloat16 smd[];
    const uint32_t smb = smem_u32(smd);

    const int tid  = threadIdx.x;
    const int w    = tid >> 5, lane = tid & 31;
    const int wm   = w >> 2, wn = w & 3;
    const int m0   = blockIdx.x * 128;
    const int n0   = blockIdx.y * 128;
    const int z    = blockIdx.z;

    const __nv_bfloat16* srcs[4] = {
        g_xh + (size_t)m0 * DIM,
        g_xl + (size_t)m0 * DIM,
        g_wth + (size_t)z * DIM * DIM + (size_t)n0 * DIM,
        g_wtl + (size_t)z * DIM * DIM + (size_t)n0 * DIM
    };

    const int a_row = lane & 15, a_kh = (lane >> 4) * 8;
    const int b_row = lane & 7,  b_kh = ((lane >> 3) & 1) * 8;

    float acc[4][4][4] = {};

    qkv_cp_blk(smb, srcs, 0, tid); CP_COMMIT();

    const int NB = DIM / BK;   // 32
    for (int blk = 0; blk < NB; blk++) {
        CP_WAIT(0);
        __syncthreads();
        // prefetch next block into the other buffer (its old contents were
        // consumed at blk-1, guaranteed finished by the sync above)
        if (blk + 1 < NB) {
            qkv_cp_blk(smb + ((blk + 1) & 1) * QBUF * 2, srcs,
                       (blk + 1) * BK, tid);
            CP_COMMIT();
        }

        const uint32_t bb = smb + (blk & 1) * QBUF * 2;
        #pragma unroll
        for (int kk = 0; kk < BK; kk += 16) {
            uint32_t ah[4][4], al[4][4];
            #pragma unroll
            for (int mt = 0; mt < 4; mt++) {
                int roff = ((wm * 64 + mt * 16 + a_row) * LDS + kk + a_kh) * 2;
                ldsm_x4(ah[mt], bb + roff);
                ldsm_x4(al[mt], bb + QREG * 2 + roff);
            }
            uint32_t bh[4][2], bl[4][2];
            #pragma unroll
            for (int nt = 0; nt < 4; nt++) {
                int roff = ((wn * 32 + nt * 8 + b_row) * LDS + kk + b_kh) * 2;
                ldsm_x2(bh[nt], bb + 2 * QREG * 2 + roff);
                ldsm_x2(bl[nt], bb + 3 * QREG * 2 + roff);
            }
            #pragma unroll
            for (int mt = 0; mt < 4; mt++)
                #pragma unroll
                for (int nt = 0; nt < 4; nt++) {
                    mma_bf16(acc[mt][nt], ah[mt], bh[nt]);
                    mma_bf16(acc[mt][nt], ah[mt], bl[nt]);
                    mma_bf16(acc[mt][nt], al[mt], bh[nt]);
                }
        }
    }

    // epilogue -> bf16 hi/lo
    const int em = lane >> 2, en = (lane & 3) * 2;
    #pragma unroll
    for (int mt = 0; mt < 4; mt++) {
        #pragma unroll
        for (int nt = 0; nt < 4; nt++) {
            int mg0 = m0 + wm * 64 + mt * 16 + em;
            int ng  = n0 + wn * 32 + nt * 8 + en;
            int h = ng >> 6, hd = ng & 63;
            #pragma unroll
            for (int half = 0; half < 2; half++) {
                int mg = mg0 + half * 8;
                int b = mg >> 10, s = mg & 1023;
                int bhI = b * NH + h;
                float c0 = acc[mt][nt][half * 2 + 0];
                float c1 = acc[mt][nt][half * 2 + 1];
                __nv_bfloat16 h0 = __float2bfloat16(c0);
                __nv_bfloat16 h1 = __float2bfloat16(c1);
                __nv_bfloat16 l0 = __float2bfloat16(c0 - __bfloat162float(h0));
                __nv_bfloat16 l1 = __float2bfloat16(c1 - __bfloat162float(h1));
                if (z == 2) {
                    size_t base = ((size_t)bhI * HD + hd) * SEQ + s;
                    g_vth[base] = h0; g_vth[base + SEQ] = h1;
                    g_vtl[base] = l0; g_vtl[base + SEQ] = l1;
                } else {
                    size_t off = ((size_t)bhI * SEQ + s) * HD + hd;
                    __nv_bfloat16* dh = (z ? g_kh : g_qh) + off;
                    __nv_bfloat16* dl = (z ? g_kl : g_ql) + off;
                    *(uint32_t*)dh = pack_bf16(h0, h1);
                    *(uint32_t*)dl = pack_bf16(l0, l1);
                }
            }
        }
    }
}

// ---------------------------------------------------------------------------
// Attention: mma.sync split-bf16, poly-exp, cp.async distance-1, 1 sync/iter.
// ---------------------------------------------------------------------------
#define ATS 72
#define SM_K  (64 * ATS)          // 4608 elems per region
#define AQ_REG (128 * ATS)        // 9216 elems per Q region
#define ABUF0 (2 * AQ_REG)        // elem offset of kv buf 0
#define ABUF  (4 * SM_K)          // elems per kv buffer
#define ATTN_SMEM ((ABUF0 + 2 * ABUF) * 2)

__device__ __forceinline__ void attn_cp_tile(
    uint32_t dstb, const __nv_bfloat16* Kh, const __nv_bfloat16* Kl,
    const __nv_bfloat16* Vh, const __nv_bfloat16* Vl, int kt, int tid)
{
    #pragma unroll
    for (int i = tid; i < 512; i += 256) {
        int r = i >> 3, c8 = (i & 7) * 8;
        uint32_t d = dstb + (r * ATS + c8) * 2;
        cp16(d,                Kh + (size_t)(kt * 64 + r) * HD + c8);
        cp16(d + SM_K * 2,     Kl + (size_t)(kt * 64 + r) * HD + c8);
        cp16(d + 2 * SM_K * 2, Vh + (size_t)r * SEQ + kt * 64 + c8);
        cp16(d + 3 * SM_K * 2, Vl + (size_t)r * SEQ + kt * 64 + c8);
    }
}

__global__ __launch_bounds__(256, 2) void attn_mma_kernel(
    const float* __restrict__ mask, float* __restrict__ out)
{
    extern __shared__ __nv_bfloat16 smd[];
    const uint32_t smb = smem_u32(smd);

    const int tid = threadIdx.x, w = tid >> 5, lane = tid & 31;
    const int qt = blockIdx.x, bh = blockIdx.y;
    const int b = bh >> 4, h = bh & 15;
    const int gr = lane >> 2, gc2 = (lane & 3) * 2;

    const __nv_bfloat16* Qh = g_qh + ((size_t)bh * SEQ + qt * 128) * HD;
    const __nv_bfloat16* Ql = g_ql + ((size_t)bh * SEQ + qt * 128) * HD;
    const __nv_bfloat16* Kh = g_kh + (size_t)bh * SEQ * HD;
    const __nv_bfloat16* Kl = g_kl + (size_t)bh * SEQ * HD;
    const __nv_bfloat16* Vh = g_vth + (size_t)bh * HD * SEQ;
    const __nv_bfloat16* Vl = g_vtl + (size_t)bh * HD * SEQ;

    // group 0: Q tiles; group 1: KV tile 0
    #pragma unroll
    for (int i = tid; i < 1024; i += 256) {
        int r = i >> 3, c8 = (i & 7) * 8;
        cp16(smb + (r * ATS + c8) * 2,            Qh + (size_t)r * HD + c8);
        cp16(smb + (AQ_REG + r * ATS + c8) * 2,   Ql + (size_t)r * HD + c8);
    }
    CP_COMMIT();
    attn_cp_tile(smb + ABUF0 * 2, Kh, Kl, Vh, Vl, 0, tid); CP_COMMIT();

    CP_WAIT(1);              // Q ready
    __syncthreads();

    uint32_t qh[4][4], ql[4][4];
    {
        const int ar = w * 16 + (lane & 15);
        const int ac = ((lane >> 4) & 1) * 8;
        #pragma unroll
        for (int ks = 0; ks < 4; ks++) {
            ldsm_x4(qh[ks], smb + (ar * ATS + ks * 16 + ac) * 2);
            ldsm_x4(ql[ks], smb + (AQ_REG + ar * ATS + ks * 16 + ac) * 2);
        }
    }

    float ctx[8][4] = {};
    float rs0 = 0.f, rs1 = 0.f;

    const float* Mb = mask + (size_t)b * SEQ * SEQ
                      + (size_t)(qt * 128 + w * 16 + gr) * SEQ + gc2;

    const int br = (lane & 7) + ((lane >> 4) << 3);
    const int bc = ((lane >> 3) & 1) * 8;

    for (int kt = 0; kt < 16; kt++) {
        CP_WAIT(0);
        __syncthreads();
        // prefetch next tile into the other buffer (its old contents were
        // consumed at kt-1, guaranteed done by the sync above)
        if (kt + 1 < 16) {
            attn_cp_tile(smb + (ABUF0 + ((kt + 1) & 1) * ABUF) * 2,
                         Kh, Kl, Vh, Vl, kt + 1, tid);
            CP_COMMIT();
        }

        const uint32_t bb = smb + (ABUF0 + (kt & 1) * ABUF) * 2;

        // ---- scores = Q K^T (split-bf16, 3 MMAs) ----
        float acc[8][4] = {};
        #pragma unroll
        for (int ks = 0; ks < 4; ks++) {
            #pragma unroll
            for (int ntp = 0; ntp < 4; ntp++) {
                uint32_t kh4[4], kl4[4];
                int off = ((ntp * 16 + br) * ATS + ks * 16 + bc) * 2;
                ldsm_x4(kh4, bb + off);
                ldsm_x4(kl4, bb + SM_K * 2 + off);
                mma_bf16(acc[ntp * 2],     qh[ks], &kh4[0]);
                mma_bf16(acc[ntp * 2],     qh[ks], &kl4[0]);
                mma_bf16(acc[ntp * 2],     ql[ks], &kh4[0]);
                mma_bf16(acc[ntp * 2 + 1], qh[ks], &kh4[2]);
                mma_bf16(acc[ntp * 2 + 1], qh[ks], &kl4[2]);
                mma_bf16(acc[ntp * 2 + 1], ql[ks], &kh4[2]);
            }
        }

        // ---- e = poly_exp(s/8) * mask; row sums; build P frags ----
        uint32_t ph[4][4], pl[4][4];
        const float* Mk = Mb + kt * 64;
        #pragma unroll
        for (int nt = 0; nt < 8; nt++) {
            float2 m0 = *(const float2*)&Mk[nt * 8];
            float2 m1 = *(const float2*)&Mk[8 * SEQ + nt * 8];
            float e0 = fexp8(acc[nt][0]) * m0.x;
            float e1 = fexp8(acc[nt][1]) * m0.y;
            float e2 = fexp8(acc[nt][2]) * m1.x;
            float e3 = fexp8(acc[nt][3]) * m1.y;
            rs0 += e0 + e1;
            rs1 += e2 + e3;
            uint32_t h01 = cvt_bf16x2(e0, e1);
            uint32_t h23 = cvt_bf16x2(e2, e3);
            float f0 = __uint_as_float(h01 << 16);
            float f1 = __uint_as_float(h01 & 0xFFFF0000u);
            float f2 = __uint_as_float(h23 << 16);
            float f3 = __uint_as_float(h23 & 0xFFFF0000u);
            uint32_t l01 = cvt_bf16x2(e0 - f0, e1 - f1);
            uint32_t l23 = cvt_bf16x2(e2 - f2, e3 - f3);
            int u = nt >> 1, sel = (nt & 1) * 2;
            ph[u][sel]     = h01;
            ph[u][sel + 1] = h23;
            pl[u][sel]     = l01;
            pl[u][sel + 1] = l23;
        }

        // ---- ctx += P V (split-bf16, 3 MMAs) ----
        #pragma unroll
        for (int u = 0; u < 4; u++) {
            #pragma unroll
            for (int dtp = 0; dtp < 4; dtp++) {
                uint32_t vh4[4], vl4[4];
                int off = ((dtp * 16 + br) * ATS + u * 16 + bc) * 2;
                ldsm_x4(vh4, bb + 2 * SM_K * 2 + off);
                ldsm_x4(vl4, bb + 3 * SM_K * 2 + off);
                mma_bf16(ctx[dtp * 2],     ph[u], &vh4[0]);
                mma_bf16(ctx[dtp * 2],     ph[u], &vl4[0]);
                mma_bf16(ctx[dtp * 2],     pl[u], &vh4[0]);
                mma_bf16(ctx[dtp * 2 + 1], ph[u], &vh4[2]);
                mma_bf16(ctx[dtp * 2 + 1], ph[u], &vl4[2]);
                mma_bf16(ctx[dtp * 2 + 1], pl[u], &vh4[2]);
            }
        }
    }

    // ---- denominators + output ----
    rs0 += __shfl_xor_sync(0xffffffffu, rs0, 1);
    rs0 += __shfl_xor_sync(0xffffffffu, rs0, 2);
    rs1 += __shfl_xor_sync(0xffffffffu, rs1, 1);
    rs1 += __shfl_xor_sync(0xffffffffu, rs1, 2);
    float inv0 = 1.0f / (rs0 + 1e-8f);
    float inv1 = 1.0f / (rs1 + 1e-8f);

    const int s0 = qt * 128 + w * 16 + gr;
    float* O = out + (((size_t)b * SEQ + s0) * NH + h) * HD + gc2;
    #pragma unroll
    for (int dt = 0; dt < 8; dt++) {
        *(float2*)&O[dt * 8] =
            make_float2(ctx[dt][0] * inv0, ctx[dt][1] * inv0);
        *(float2*)&O[(size_t)8 * NH * HD + dt * 8] =
            make_float2(ctx[dt][2] * inv1, ctx[dt][3] * inv1);
    }
}

// ---------------------------------------------------------------------------
extern "C" void kernel_launch(void* const* d_in, const int* in_sizes, int n_in,
                              void* d_out, int out_size)
{
    const float* x    = (const float*)d_in[0];
    const float* mask = (const float*)d_in[1];
    const float* Wq   = (const float*)d_in[2];
    const float* Wk   = (const float*)d_in[3];
    const float* Wv   = (const float*)d_in[4];
    float* out = (float*)d_out;

    static int init = 0;
    if (!init) {
        cudaFuncSetAttribute(qkv_mma_kernel,
            cudaFuncAttributeMaxDynamicSharedMemorySize, QKV_SMEM);
        cudaFuncSetAttribute(attn_mma_kernel,
            cudaFuncAttributeMaxDynamicSharedMemorySize, ATTN_SMEM);
        init = 1;
    }

    convert_x_kernel<<<BATCH * SEQ, 256>>>(x);
    convert_wt_kernel<<<dim3(32, 32, 3), dim3(32, 8)>>>(Wq, Wk, Wv);
    qkv_mma_kernel<<<dim3(64, 8, 3), 256, QKV_SMEM>>>();
    attn_mma_kernel<<<dim3(8, 128), 256, ATTN_SMEM>>>(mask, out);
}

// round 8
// speedup vs baseline: 2.9532x; 1.0314x over previous
#include <cuda_runtime.h>
#include <cuda_bf16.h>
#include <cstdint>

#define BATCH 8
#define SEQ   1024
#define DIM   1024
#define NH    16
#define HD    64

// split-bf16 operands for MMA projections
__device__ __nv_bfloat16 g_xh[BATCH*SEQ*DIM];     // x hi   [m][k]
__device__ __nv_bfloat16 g_xl[BATCH*SEQ*DIM];     // x lo
__device__ __nv_bfloat16 g_wth[3*DIM*DIM];        // W^T hi [n][k]
__device__ __nv_bfloat16 g_wtl[3*DIM*DIM];        // W^T lo

// attention operands (written by QKV GEMM epilogue)
__device__ __nv_bfloat16 g_qh [BATCH*NH*SEQ*HD];  // Q hi  [bh][s][hd]
__device__ __nv_bfloat16 g_ql [BATCH*NH*SEQ*HD];
__device__ __nv_bfloat16 g_kh [BATCH*NH*SEQ*HD];  // K hi  [bh][s][hd]
__device__ __nv_bfloat16 g_kl [BATCH*NH*SEQ*HD];
__device__ __nv_bfloat16 g_vth[BATCH*NH*HD*SEQ];  // V^T hi [bh][hd][s]
__device__ __nv_bfloat16 g_vtl[BATCH*NH*HD*SEQ];

// binary mask packed to u8
__device__ uint8_t g_m8[BATCH*SEQ*SEQ];

// ---------------------------------------------------------------------------
// helpers
// ---------------------------------------------------------------------------
__device__ __forceinline__ uint32_t smem_u32(const void* p) {
    uint32_t a;
    asm("{ .reg .u64 t; cvta.to.shared.u64 t, %1; cvt.u32.u64 %0, t; }"
        : "=r"(a) : "l"(p));
    return a;
}
__device__ __forceinline__ void ldsm_x4(uint32_t a[4], uint32_t addr) {
    asm volatile("ldmatrix.sync.aligned.m8n8.x4.shared.b16 {%0,%1,%2,%3}, [%4];"
                 : "=r"(a[0]), "=r"(a[1]), "=r"(a[2]), "=r"(a[3]) : "r"(addr));
}
__device__ __forceinline__ void ldsm_x2(uint32_t b[2], uint32_t addr) {
    asm volatile("ldmatrix.sync.aligned.m8n8.x2.shared.b16 {%0,%1}, [%2];"
                 : "=r"(b[0]), "=r"(b[1]) : "r"(addr));
}
__device__ __forceinline__ void mma_bf16(float c[4], const uint32_t a[4],
                                         const uint32_t b[2]) {
    asm volatile(
        "mma.sync.aligned.m16n8k16.row.col.f32.bf16.bf16.f32 "
        "{%0,%1,%2,%3}, {%4,%5,%6,%7}, {%8,%9}, {%0,%1,%2,%3};"
        : "+f"(c[0]), "+f"(c[1]), "+f"(c[2]), "+f"(c[3])
        : "r"(a[0]), "r"(a[1]), "r"(a[2]), "r"(a[3]), "r"(b[0]), "r"(b[1]));
}
__device__ __forceinline__ uint32_t pack_bf16(__nv_bfloat16 a, __nv_bfloat16 b) {
    __nv_bfloat162 p; p.x = a; p.y = b;
    return *(uint32_t*)&p;
}
// packed {lo, hi} bf16x2 from two floats
__device__ __forceinline__ uint32_t cvt_bf16x2(float lo, float hi) {
    uint32_t r;
    asm("cvt.rn.bf16x2.f32 %0, %1, %2;" : "=r"(r) : "f"(hi), "f"(lo));
    return r;
}
__device__ __forceinline__ void cp16(uint32_t dst, const void* src) {
    asm volatile("cp.async.cg.shared.global [%0], [%1], 16;"
                 :: "r"(dst), "l"(src));
}
#define CP_COMMIT() asm volatile("cp.async.commit_group;" ::: "memory")
#define CP_WAIT(n)  asm volatile("cp.async.wait_group %0;" :: "n"(n) : "memory")

// exp(s/8) via exp2 poly: t = s*log2e/8; magic round; degree-5 Taylor on [-.5,.5]
__device__ __forceinline__ float fexp8(float s) {
    float t = s * 0.18033688011112042f;          // log2(e)/8
    float k = t + 12582912.0f;                   // 1.5*2^23 magic round
    float j = k - 12582912.0f;
    float f = t - j;
    float p = 1.3333558147e-3f;
    p = fmaf(p, f, 9.6181291076e-3f);
    p = fmaf(p, f, 5.5504108665e-2f);
    p = fmaf(p, f, 2.4022650696e-1f);
    p = fmaf(p, f, 6.9314718056e-1f);
    p = fmaf(p, f, 1.0f);
    int ib = __float_as_int(k) - 0x4B400000;
    float scale = __int_as_float((ib + 127) << 23);
    return p * scale;
}

// ---------------------------------------------------------------------------
// Preprocess: split x -> (hi, lo) bf16
// ---------------------------------------------------------------------------
__global__ __launch_bounds__(256) void convert_x_kernel(const float* __restrict__ x) {
    int i = (blockIdx.x * 256 + threadIdx.x) * 4;
    float4 v = *(const float4*)(x + i);
    __nv_bfloat16 h0 = __float2bfloat16(v.x), h1 = __float2bfloat16(v.y);
    __nv_bfloat16 h2 = __float2bfloat16(v.z), h3 = __float2bfloat16(v.w);
    __nv_bfloat162 hi01, hi23, lo01, lo23;
    hi01.x = h0; hi01.y = h1; hi23.x = h2; hi23.y = h3;
    lo01.x = __float2bfloat16(v.x - __bfloat162float(h0));
    lo01.y = __float2bfloat16(v.y - __bfloat162float(h1));
    lo23.x = __float2bfloat16(v.z - __bfloat162float(h2));
    lo23.y = __float2bfloat16(v.w - __bfloat162float(h3));
    *(__nv_bfloat162*)(g_xh + i)     = hi01;
    *(__nv_bfloat162*)(g_xh + i + 2) = hi23;
    *(__nv_bfloat162*)(g_xl + i)     = lo01;
    *(__nv_bfloat162*)(g_xl + i + 2) = lo23;
}

// Preprocess: mask f32 (0/1) -> u8
__global__ __launch_bounds__(256) void convert_mask_kernel(const float* __restrict__ m) {
    int i = (blockIdx.x * 256 + threadIdx.x) * 4;
    float4 v = *(const float4*)(m + i);
    uint32_t p = (uint32_t)(v.x != 0.0f)
               | ((uint32_t)(v.y != 0.0f) << 8)
               | ((uint32_t)(v.z != 0.0f) << 16)
               | ((uint32_t)(v.w != 0.0f) << 24);
    *(uint32_t*)(g_m8 + i) = p;
}

// Preprocess: W[k][n] -> Wt[n][k] split into (hi, lo) bf16
__global__ __launch_bounds__(256) void convert_wt_kernel(
    const float* __restrict__ Wq, const float* __restrict__ Wk,
    const float* __restrict__ Wv)
{
    __shared__ float t[32][33];
    const int z = blockIdx.z;
    const float* __restrict__ W = (z == 0) ? Wq : (z == 1 ? Wk : Wv);
    const int n0 = blockIdx.x * 32, k0 = blockIdx.y * 32;
    const int tx = threadIdx.x, ty = threadIdx.y;   // block (32, 8)

    #pragma unroll
    for (int i = ty; i < 32; i += 8)
        t[i][tx] = W[(size_t)(k0 + i) * DIM + n0 + tx];
    __syncthreads();

    __nv_bfloat16* wh = g_wth + (size_t)z * DIM * DIM;
    __nv_bfloat16* wl = g_wtl + (size_t)z * DIM * DIM;
    #pragma unroll
    for (int i = ty; i < 32; i += 8) {
        float v = t[tx][i];
        __nv_bfloat16 h = __float2bfloat16(v);
        wh[(size_t)(n0 + i) * DIM + k0 + tx] = h;
        wl[(size_t)(n0 + i) * DIM + k0 + tx] = __float2bfloat16(v - __bfloat162float(h));
    }
}

// ---------------------------------------------------------------------------
// QKV projection GEMM, cp.async distance-1 double buffer, 1 sync/iter.
// ---------------------------------------------------------------------------
#define BK 32
#define LDS 40
#define QREG (128 * LDS)          // 5120 elems per region
#define QBUF (4 * QREG)           // 20480 elems per buffer
#define QKV_SMEM (2 * QBUF * 2)   // bytes

__device__ __forceinline__ void qkv_cp_blk(
    uint32_t dstb, const __nv_bfloat16* const* srcs, int k0, int tid)
{
    #pragma unroll
    for (int t = 0; t < 4; t++) {
        const __nv_bfloat16* s = srcs[t] + k0;
        #pragma unroll
        for (int i = tid; i < 512; i += 256) {
            int r = i >> 2, c8 = (i & 3) * 8;
            cp16(dstb + (t * QREG + r * LDS + c8) * 2,
                 s + (size_t)r * DIM + c8);
        }
    }
}

__global__ __launch_bounds__(256, 2) void qkv_mma_kernel()
{
    extern __shared__ __nv_bfloat16 smd[];
    const uint32_t smb = smem_u32(smd);

    const int tid  = threadIdx.x;
    const int w    = tid >> 5, lane = tid & 31;
    const int wm   = w >> 2, wn = w & 3;
    const int m0   = blockIdx.x * 128;
    const int n0   = blockIdx.y * 128;
    const int z    = blockIdx.z;

    const __nv_bfloat16* srcs[4] = {
        g_xh + (size_t)m0 * DIM,
        g_xl + (size_t)m0 * DIM,
        g_wth + (size_t)z * DIM * DIM + (size_t)n0 * DIM,
        g_wtl + (size_t)z * DIM * DIM + (size_t)n0 * DIM
    };

    const int a_row = lane & 15, a_kh = (lane >> 4) * 8;
    const int b_row = lane & 7,  b_kh = ((lane >> 3) & 1) * 8;

    float acc[4][4][4] = {};

    qkv_cp_blk(smb, srcs, 0, tid); CP_COMMIT();

    const int NB = DIM / BK;   // 32
    for (int blk = 0; blk < NB; blk++) {
        CP_WAIT(0);
        __syncthreads();
        if (blk + 1 < NB) {
            qkv_cp_blk(smb + ((blk + 1) & 1) * QBUF * 2, srcs,
                       (blk + 1) * BK, tid);
            CP_COMMIT();
        }

        const uint32_t bb = smb + (blk & 1) * QBUF * 2;
        #pragma unroll
        for (int kk = 0; kk < BK; kk += 16) {
            uint32_t ah[4][4], al[4][4];
            #pragma unroll
            for (int mt = 0; mt < 4; mt++) {
                int roff = ((wm * 64 + mt * 16 + a_row) * LDS + kk + a_kh) * 2;
                ldsm_x4(ah[mt], bb + roff);
                ldsm_x4(al[mt], bb + QREG * 2 + roff);
            }
            uint32_t bh[4][2], bl[4][2];
            #pragma unroll
            for (int nt = 0; nt < 4; nt++) {
                int roff = ((wn * 32 + nt * 8 + b_row) * LDS + kk + b_kh) * 2;
                ldsm_x2(bh[nt], bb + 2 * QREG * 2 + roff);
                ldsm_x2(bl[nt], bb + 3 * QREG * 2 + roff);
            }
            #pragma unroll
            for (int mt = 0; mt < 4; mt++)
                #pragma unroll
                for (int nt = 0; nt < 4; nt++) {
                    mma_bf16(acc[mt][nt], ah[mt], bh[nt]);
                    mma_bf16(acc[mt][nt], ah[mt], bl[nt]);
                    mma_bf16(acc[mt][nt], al[mt], bh[nt]);
                }
        }
    }

    // epilogue -> bf16 hi/lo
    const int em = lane >> 2, en = (lane & 3) * 2;
    #pragma unroll
    for (int mt = 0; mt < 4; mt++) {
        #pragma unroll
        for (int nt = 0; nt < 4; nt++) {
            int mg0 = m0 + wm * 64 + mt * 16 + em;
            int ng  = n0 + wn * 32 + nt * 8 + en;
            int h = ng >> 6, hd = ng & 63;
            #pragma unroll
            for (int half = 0; half < 2; half++) {
                int mg = mg0 + half * 8;
                int b = mg >> 10, s = mg & 1023;
                int bhI = b * NH + h;
                float c0 = acc[mt][nt][half * 2 + 0];
                float c1 = acc[mt][nt][half * 2 + 1];
                __nv_bfloat16 h0 = __float2bfloat16(c0);
                __nv_bfloat16 h1 = __float2bfloat16(c1);
                __nv_bfloat16 l0 = __float2bfloat16(c0 - __bfloat162float(h0));
                __nv_bfloat16 l1 = __float2bfloat16(c1 - __bfloat162float(h1));
                if (z == 2) {
                    size_t base = ((size_t)bhI * HD + hd) * SEQ + s;
                    g_vth[base] = h0; g_vth[base + SEQ] = h1;
                    g_vtl[base] = l0; g_vtl[base + SEQ] = l1;
                } else {
                    size_t off = ((size_t)bhI * SEQ + s) * HD + hd;
                    __nv_bfloat16* dh = (z ? g_kh : g_qh) + off;
                    __nv_bfloat16* dl = (z ? g_kl : g_ql) + off;
                    *(uint32_t*)dh = pack_bf16(h0, h1);
                    *(uint32_t*)dl = pack_bf16(l0, l1);
                }
            }
        }
    }
}

// ---------------------------------------------------------------------------
// Attention: mma.sync split-bf16, poly-exp, mask-in-smem (u8), cp.async.
//   smem: 2 buffers x { Kh,Kl,Vh,Vl [64][72] bf16 (36864 B) + mask 8 KB }.
//   Q (128x72 hi/lo = 36864 B) staged in buffer 0's space at startup,
//   consumed into registers, then the space is recycled by the KV pipeline.
// ---------------------------------------------------------------------------
#define ATS 72
#define SM_K  (64 * ATS)             // 4608 elems per region
#define AQ_REG (128 * ATS)           // 9216 elems per Q region
#define AMASK_OFF (4 * SM_K * 2)     // 36864: mask byte offset within buffer
#define ABUF_BYTES (AMASK_OFF + 8192)  // 45056
#define ATTN_SMEM (2 * ABUF_BYTES)   // 90112

__device__ __forceinline__ void attn_cp_tile(
    uint32_t dstb, const __nv_bfloat16* Kh, const __nv_bfloat16* Kl,
    const __nv_bfloat16* Vh, const __nv_bfloat16* Vl,
    const uint8_t* M8, int kt, int tid)
{
    #pragma unroll
    for (int i = tid; i < 512; i += 256) {
        int r = i >> 3, c8 = (i & 7) * 8;
        uint32_t d = dstb + (r * ATS + c8) * 2;
        cp16(d,                Kh + (size_t)(kt * 64 + r) * HD + c8);
        cp16(d + SM_K * 2,     Kl + (size_t)(kt * 64 + r) * HD + c8);
        cp16(d + 2 * SM_K * 2, Vh + (size_t)r * SEQ + kt * 64 + c8);
        cp16(d + 3 * SM_K * 2, Vl + (size_t)r * SEQ + kt * 64 + c8);
    }
    // mask tile: 128 rows x 64 u8
    #pragma unroll
    for (int i = tid; i < 512; i += 256) {
        int r = i >> 2, c16 = (i & 3) * 16;
        cp16(dstb + AMASK_OFF + r * 64 + c16,
             M8 + (size_t)r * SEQ + kt * 64 + c16);
    }
}

__global__ __launch_bounds__(256, 2) void attn_mma_kernel(float* __restrict__ out)
{
    extern __shared__ __nv_bfloat16 smd[];
    const uint32_t smb = smem_u32(smd);
    const char* sb = (const char*)smd;

    const int tid = threadIdx.x, w = tid >> 5, lane = tid & 31;
    const int qt = blockIdx.x, bh = blockIdx.y;
    const int b = bh >> 4, h = bh & 15;
    const int gr = lane >> 2, gc2 = (lane & 3) * 2;

    const __nv_bfloat16* Qh = g_qh + ((size_t)bh * SEQ + qt * 128) * HD;
    const __nv_bfloat16* Ql = g_ql + ((size_t)bh * SEQ + qt * 128) * HD;
    const __nv_bfloat16* Kh = g_kh + (size_t)bh * SEQ * HD;
    const __nv_bfloat16* Kl = g_kl + (size_t)bh * SEQ * HD;
    const __nv_bfloat16* Vh = g_vth + (size_t)bh * HD * SEQ;
    const __nv_bfloat16* Vl = g_vtl + (size_t)bh * HD * SEQ;
    const uint8_t* M8 = g_m8 + (size_t)b * SEQ * SEQ + (size_t)(qt * 128) * SEQ;

    // ---- stage Q in buffer-0 space, consume to registers ----
    #pragma unroll
    for (int i = tid; i < 1024; i += 256) {
        int r = i >> 3, c8 = (i & 7) * 8;
        cp16(smb + (r * ATS + c8) * 2,          Qh + (size_t)r * HD + c8);
        cp16(smb + (AQ_REG + r * ATS + c8) * 2, Ql + (size_t)r * HD + c8);
    }
    CP_COMMIT();
    CP_WAIT(0);
    __syncthreads();

    uint32_t qh[4][4], ql[4][4];
    {
        const int ar = w * 16 + (lane & 15);
        const int ac = ((lane >> 4) & 1) * 8;
        #pragma unroll
        for (int ks = 0; ks < 4; ks++) {
            ldsm_x4(qh[ks], smb + (ar * ATS + ks * 16 + ac) * 2);
            ldsm_x4(ql[ks], smb + (AQ_REG + ar * ATS + ks * 16 + ac) * 2);
        }
    }
    __syncthreads();   // all warps done reading Q before buffer 0 is recycled

    attn_cp_tile(smb, Kh, Kl, Vh, Vl, M8, 0, tid); CP_COMMIT();

    float ctx[8][4] = {};
    float rs0 = 0.f, rs1 = 0.f;

    const int br = (lane & 7) + ((lane >> 4) << 3);
    const int bc = ((lane >> 3) & 1) * 8;
    const int mrow_off = (w * 16 + gr) * 64 + gc2;

    for (int kt = 0; kt < 16; kt++) {
        CP_WAIT(0);
        __syncthreads();
        if (kt + 1 < 16) {
            attn_cp_tile(smb + ((kt + 1) & 1) * ABUF_BYTES,
                         Kh, Kl, Vh, Vl, M8, kt + 1, tid);
            CP_COMMIT();
        }

        const uint32_t bb = smb + (kt & 1) * ABUF_BYTES;

        // ---- scores = Q K^T (split-bf16, 3 MMAs) ----
        float acc[8][4] = {};
        #pragma unroll
        for (int ks = 0; ks < 4; ks++) {
            #pragma unroll
            for (int ntp = 0; ntp < 4; ntp++) {
                uint32_t kh4[4], kl4[4];
                int off = ((ntp * 16 + br) * ATS + ks * 16 + bc) * 2;
                ldsm_x4(kh4, bb + off);
                ldsm_x4(kl4, bb + SM_K * 2 + off);
                mma_bf16(acc[ntp * 2],     qh[ks], &kh4[0]);
                mma_bf16(acc[ntp * 2],     qh[ks], &kl4[0]);
                mma_bf16(acc[ntp * 2],     ql[ks], &kh4[0]);
                mma_bf16(acc[ntp * 2 + 1], qh[ks], &kh4[2]);
                mma_bf16(acc[ntp * 2 + 1], qh[ks], &kl4[2]);
                mma_bf16(acc[ntp * 2 + 1], ql[ks], &kh4[2]);
            }
        }

        // ---- e = poly_exp(s/8) * mask (u8 from smem); sums; P frags ----
        const char* mp = sb + (kt & 1) * ABUF_BYTES + AMASK_OFF + mrow_off;
        uint32_t ph[4][4], pl[4][4];
        #pragma unroll
        for (int nt = 0; nt < 8; nt++) {
            uint32_t mm01 = *(const uint16_t*)(mp + nt * 8);
            uint32_t mm23 = *(const uint16_t*)(mp + 512 + nt * 8);
            float e0 = fexp8(acc[nt][0]) * (float)(mm01 & 0xFF);
            float e1 = fexp8(acc[nt][1]) * (float)(mm01 >> 8);
            float e2 = fexp8(acc[nt][2]) * (float)(mm23 & 0xFF);
            float e3 = fexp8(acc[nt][3]) * (float)(mm23 >> 8);
            rs0 += e0 + e1;
            rs1 += e2 + e3;
            uint32_t h01 = cvt_bf16x2(e0, e1);
            uint32_t h23 = cvt_bf16x2(e2, e3);
            float f0 = __uint_as_float(h01 << 16);
            float f1 = __uint_as_float(h01 & 0xFFFF0000u);
            float f2 = __uint_as_float(h23 << 16);
            float f3 = __uint_as_float(h23 & 0xFFFF0000u);
            uint32_t l01 = cvt_bf16x2(e0 - f0, e1 - f1);
            uint32_t l23 = cvt_bf16x2(e2 - f2, e3 - f3);
            int u = nt >> 1, sel = (nt & 1) * 2;
            ph[u][sel]     = h01;
            ph[u][sel + 1] = h23;
            pl[u][sel]     = l01;
            pl[u][sel + 1] = l23;
        }

        // ---- ctx += P V (split-bf16, 3 MMAs) ----
        #pragma unroll
        for (int u = 0; u < 4; u++) {
            #pragma unroll
            for (int dtp = 0; dtp < 4; dtp++) {
                uint32_t vh4[4], vl4[4];
                int off = ((dtp * 16 + br) * ATS + u * 16 + bc) * 2;
                ldsm_x4(vh4, bb + 2 * SM_K * 2 + off);
                ldsm_x4(vl4, bb + 3 * SM_K * 2 + off);
                mma_bf16(ctx[dtp * 2],     ph[u], &vh4[0]);
                mma_bf16(ctx[dtp * 2],     ph[u], &vl4[0]);
                mma_bf16(ctx[dtp * 2],     pl[u], &vh4[0]);
                mma_bf16(ctx[dtp * 2 + 1], ph[u], &vh4[2]);
                mma_bf16(ctx[dtp * 2 + 1], ph[u], &vl4[2]);
                mma_bf16(ctx[dtp * 2 + 1], pl[u], &vh4[2]);
            }
        }
    }

    // ---- denominators + output ----
    rs0 += __shfl_xor_sync(0xffffffffu, rs0, 1);
    rs0 += __shfl_xor_sync(0xffffffffu, rs0, 2);
    rs1 += __shfl_xor_sync(0xffffffffu, rs1, 1);
    rs1 += __shfl_xor_sync(0xffffffffu, rs1, 2);
    float inv0 = 1.0f / (rs0 + 1e-8f);
    float inv1 = 1.0f / (rs1 + 1e-8f);

    const int s0 = qt * 128 + w * 16 + gr;
    float* O = out + (((size_t)b * SEQ + s0) * NH + h) * HD + gc2;
    #pragma unroll
    for (int dt = 0; dt < 8; dt++) {
        *(float2*)&O[dt * 8] =
            make_float2(ctx[dt][0] * inv0, ctx[dt][1] * inv0);
        *(float2*)&O[(size_t)8 * NH * HD + dt * 8] =
            make_float2(ctx[dt][2] * inv1, ctx[dt][3] * inv1);
    }
}

// ---------------------------------------------------------------------------
extern "C" void kernel_launch(void* const* d_in, const int* in_sizes, int n_in,
                              void* d_out, int out_size)
{
    const float* x    = (const float*)d_in[0];
    const float* mask = (const float*)d_in[1];
    const float* Wq   = (const float*)d_in[2];
    const float* Wk   = (const float*)d_in[3];
    const float* Wv   = (const float*)d_in[4];
    float* out = (float*)d_out;

    static int init = 0;
    if (!init) {
        cudaFuncSetAttribute(qkv_mma_kernel,
            cudaFuncAttributeMaxDynamicSharedMemorySize, QKV_SMEM);
        cudaFuncSetAttribute(attn_mma_kernel,
            cudaFuncAttributeMaxDynamicSharedMemorySize, ATTN_SMEM);
        init = 1;
    }

    convert_x_kernel<<<BATCH * SEQ, 256>>>(x);
    convert_mask_kernel<<<BATCH * SEQ * SEQ / 1024, 256>>>(mask);
    convert_wt_kernel<<<dim3(32, 32, 3), dim3(32, 8)>>>(Wq, Wk, Wv);
    qkv_mma_kernel<<<dim3(64, 8, 3), 256, QKV_SMEM>>>();
    attn_mma_kernel<<<dim3(8, 128), 256, ATTN_SMEM>>>(out);
}

// round 9
// speedup vs baseline: 3.6891x; 1.2492x over previous
#include <cuda_runtime.h>
#include <cuda_fp16.h>
#include <cstdint>

#define BATCH 8
#define SEQ   1024
#define DIM   1024
#define NH    16
#define HD    64

// split-fp16 operands for MMA projections
__device__ __half g_xh[BATCH*SEQ*DIM];     // x hi   [m][k]
__device__ __half g_xl[BATCH*SEQ*DIM];     // x lo
__device__ __half g_wt[3*DIM*DIM];         // W^T plain fp16 [n][k]

// attention operands (written by QKV GEMM epilogue)
__device__ __half g_qh [BATCH*NH*SEQ*HD];  // Q hi  [bh][s][hd]
__device__ __half g_ql [BATCH*NH*SEQ*HD];  // Q lo
__device__ __half g_k  [BATCH*NH*SEQ*HD];  // K plain [bh][s][hd]
__device__ __half g_vth[BATCH*NH*HD*SEQ];  // V^T hi [bh][hd][s]
__device__ __half g_vtl[BATCH*NH*HD*SEQ];  // V^T lo

// binary mask packed to u8
__device__ uint8_t g_m8[BATCH*SEQ*SEQ];

// ---------------------------------------------------------------------------
// helpers
// ---------------------------------------------------------------------------
__device__ __forceinline__ uint32_t smem_u32(const void* p) {
    uint32_t a;
    asm("{ .reg .u64 t; cvta.to.shared.u64 t, %1; cvt.u32.u64 %0, t; }"
        : "=r"(a) : "l"(p));
    return a;
}
__device__ __forceinline__ void ldsm_x4(uint32_t a[4], uint32_t addr) {
    asm volatile("ldmatrix.sync.aligned.m8n8.x4.shared.b16 {%0,%1,%2,%3}, [%4];"
                 : "=r"(a[0]), "=r"(a[1]), "=r"(a[2]), "=r"(a[3]) : "r"(addr));
}
__device__ __forceinline__ void ldsm_x2(uint32_t b[2], uint32_t addr) {
    asm volatile("ldmatrix.sync.aligned.m8n8.x2.shared.b16 {%0,%1}, [%2];"
                 : "=r"(b[0]), "=r"(b[1]) : "r"(addr));
}
__device__ __forceinline__ void mma_f16(float c[4], const uint32_t a[4],
                                        const uint32_t b[2]) {
    asm volatile(
        "mma.sync.aligned.m16n8k16.row.col.f32.f16.f16.f32 "
        "{%0,%1,%2,%3}, {%4,%5,%6,%7}, {%8,%9}, {%0,%1,%2,%3};"
        : "+f"(c[0]), "+f"(c[1]), "+f"(c[2]), "+f"(c[3])
        : "r"(a[0]), "r"(a[1]), "r"(a[2]), "r"(a[3]), "r"(b[0]), "r"(b[1]));
}
__device__ __forceinline__ uint32_t pack_f16(__half a, __half b) {
    __half2 p; p.x = a; p.y = b;
    return *(uint32_t*)&p;
}
// packed {lo, hi} f16x2 from two floats (mirrors validated bf16x2 pattern)
__device__ __forceinline__ uint32_t cvt_f16x2(float lo, float hi) {
    uint32_t r;
    asm("cvt.rn.f16x2.f32 %0, %1, %2;" : "=r"(r) : "f"(hi), "f"(lo));
    return r;
}
__device__ __forceinline__ void unpack_f16x2(uint32_t p, float& a, float& b) {
    asm("{.reg .f16 l, h;\n\t mov.b32 {l, h}, %2;\n\t"
        "cvt.f32.f16 %0, l;\n\t cvt.f32.f16 %1, h;}"
        : "=f"(a), "=f"(b) : "r"(p));
}
__device__ __forceinline__ void cp16(uint32_t dst, const void* src) {
    asm volatile("cp.async.cg.shared.global [%0], [%1], 16;"
                 :: "r"(dst), "l"(src));
}
#define CP_COMMIT() asm volatile("cp.async.commit_group;" ::: "memory")
#define CP_WAIT(n)  asm volatile("cp.async.wait_group %0;" :: "n"(n) : "memory")

// exp(s/8) via exp2 poly: t = s*log2e/8; magic round; degree-5 Taylor on [-.5,.5]
__device__ __forceinline__ float fexp8(float s) {
    float t = s * 0.18033688011112042f;          // log2(e)/8
    float k = t + 12582912.0f;                   // 1.5*2^23 magic round
    float j = k - 12582912.0f;
    float f = t - j;
    float p = 1.3333558147e-3f;
    p = fmaf(p, f, 9.6181291076e-3f);
    p = fmaf(p, f, 5.5504108665e-2f);
    p = fmaf(p, f, 2.4022650696e-1f);
    p = fmaf(p, f, 6.9314718056e-1f);
    p = fmaf(p, f, 1.0f);
    int ib = __float_as_int(k) - 0x4B400000;
    float scale = __int_as_float((ib + 127) << 23);
    return p * scale;
}

// ---------------------------------------------------------------------------
// Preprocess: split x -> (hi, lo) fp16
// ---------------------------------------------------------------------------
__global__ __launch_bounds__(256) void convert_x_kernel(const float* __restrict__ x) {
    int i = (blockIdx.x * 256 + threadIdx.x) * 4;
    float4 v = *(const float4*)(x + i);
    __half h0 = __float2half_rn(v.x), h1 = __float2half_rn(v.y);
    __half h2 = __float2half_rn(v.z), h3 = __float2half_rn(v.w);
    *(uint32_t*)(g_xh + i)     = pack_f16(h0, h1);
    *(uint32_t*)(g_xh + i + 2) = pack_f16(h2, h3);
    *(uint32_t*)(g_xl + i)     = pack_f16(
        __float2half_rn(v.x - __half2float(h0)),
        __float2half_rn(v.y - __half2float(h1)));
    *(uint32_t*)(g_xl + i + 2) = pack_f16(
        __float2half_rn(v.z - __half2float(h2)),
        __float2half_rn(v.w - __half2float(h3)));
}

// Preprocess: mask f32 (0/1) -> u8
__global__ __launch_bounds__(256) void convert_mask_kernel(const float* __restrict__ m) {
    int i = (blockIdx.x * 256 + threadIdx.x) * 4;
    float4 v = *(const float4*)(m + i);
    uint32_t p = (uint32_t)(v.x != 0.0f)
               | ((uint32_t)(v.y != 0.0f) << 8)
               | ((uint32_t)(v.z != 0.0f) << 16)
               | ((uint32_t)(v.w != 0.0f) << 24);
    *(uint32_t*)(g_m8 + i) = p;
}

// Preprocess: W[k][n] -> Wt[n][k] plain fp16
__global__ __launch_bounds__(256) void convert_wt_kernel(
    const float* __restrict__ Wq, const float* __restrict__ Wk,
    const float* __restrict__ Wv)
{
    __shared__ float t[32][33];
    const int z = blockIdx.z;
    const float* __restrict__ W = (z == 0) ? Wq : (z == 1 ? Wk : Wv);
    const int n0 = blockIdx.x * 32, k0 = blockIdx.y * 32;
    const int tx = threadIdx.x, ty = threadIdx.y;   // block (32, 8)

    #pragma unroll
    for (int i = ty; i < 32; i += 8)
        t[i][tx] = W[(size_t)(k0 + i) * DIM + n0 + tx];
    __syncthreads();

    __half* wt = g_wt + (size_t)z * DIM * DIM;
    #pragma unroll
    for (int i = ty; i < 32; i += 8)
        wt[(size_t)(n0 + i) * DIM + k0 + tx] = __float2half_rn(t[tx][i]);
}

// ---------------------------------------------------------------------------
// QKV projection GEMM: fp16, x split hi/lo, W plain -> 2 MMAs per tile.
//   128x128 tile, 8 warps (2x4), warp tile 64x32, BK=32.
//   smem: 2 bufs x 3 regions (xh, xl, W) x 128 x LDS fp16 = 61440 B.
// ---------------------------------------------------------------------------
#define BK 32
#define LDS 40
#define QREG (128 * LDS)          // 5120 elems per region
#define QBUF (3 * QREG)           // 15360 elems per buffer
#define QKV_SMEM (2 * QBUF * 2)   // 61440 bytes

__device__ __forceinline__ void qkv_cp_blk(
    uint32_t dstb, const __half* const* srcs, int k0, int tid)
{
    #pragma unroll
    for (int t = 0; t < 3; t++) {
        const __half* s = srcs[t] + k0;
        #pragma unroll
        for (int i = tid; i < 512; i += 256) {
            int r = i >> 2, c8 = (i & 3) * 8;
            cp16(dstb + (t * QREG + r * LDS + c8) * 2,
                 s + (size_t)r * DIM + c8);
        }
    }
}

__global__ __launch_bounds__(256, 2) void qkv_mma_kernel()
{
    extern __shared__ __half smd[];
    const uint32_t smb = smem_u32(smd);

    const int tid  = threadIdx.x;
    const int w    = tid >> 5, lane = tid & 31;
    const int wm   = w >> 2, wn = w & 3;
    const int m0   = blockIdx.x * 128;
    const int n0   = blockIdx.y * 128;
    const int z    = blockIdx.z;

    const __half* srcs[3] = {
        g_xh + (size_t)m0 * DIM,
        g_xl + (size_t)m0 * DIM,
        g_wt + (size_t)z * DIM * DIM + (size_t)n0 * DIM
    };

    const int a_row = lane & 15, a_kh = (lane >> 4) * 8;
    const int b_row = lane & 7,  b_kh = ((lane >> 3) & 1) * 8;

    float acc[4][4][4] = {};

    qkv_cp_blk(smb, srcs, 0, tid); CP_COMMIT();

    const int NB = DIM / BK;   // 32
    for (int blk = 0; blk < NB; blk++) {
        CP_WAIT(0);
        __syncthreads();
        if (blk + 1 < NB) {
            qkv_cp_blk(smb + ((blk + 1) & 1) * QBUF * 2, srcs,
                       (blk + 1) * BK, tid);
            CP_COMMIT();
        }

        const uint32_t bb = smb + (blk & 1) * QBUF * 2;
        #pragma unroll
        for (int kk = 0; kk < BK; kk += 16) {
            uint32_t ah[4][4], al[4][4];
            #pragma unroll
            for (int mt = 0; mt < 4; mt++) {
                int roff = ((wm * 64 + mt * 16 + a_row) * LDS + kk + a_kh) * 2;
                ldsm_x4(ah[mt], bb + roff);
                ldsm_x4(al[mt], bb + QREG * 2 + roff);
            }
            uint32_t bw[4][2];
            #pragma unroll
            for (int nt = 0; nt < 4; nt++) {
                int roff = ((wn * 32 + nt * 8 + b_row) * LDS + kk + b_kh) * 2;
                ldsm_x2(bw[nt], bb + 2 * QREG * 2 + roff);
            }
            #pragma unroll
            for (int mt = 0; mt < 4; mt++)
                #pragma unroll
                for (int nt = 0; nt < 4; nt++) {
                    mma_f16(acc[mt][nt], ah[mt], bw[nt]);
                    mma_f16(acc[mt][nt], al[mt], bw[nt]);
                }
        }
    }

    // epilogue -> fp16 (q hi/lo, k plain, v^T hi/lo)
    const int em = lane >> 2, en = (lane & 3) * 2;
    #pragma unroll
    for (int mt = 0; mt < 4; mt++) {
        #pragma unroll
        for (int nt = 0; nt < 4; nt++) {
            int mg0 = m0 + wm * 64 + mt * 16 + em;
            int ng  = n0 + wn * 32 + nt * 8 + en;
            int h = ng >> 6, hd = ng & 63;
            #pragma unroll
            for (int half_i = 0; half_i < 2; half_i++) {
                int mg = mg0 + half_i * 8;
                int b = mg >> 10, s = mg & 1023;
                int bhI = b * NH + h;
                float c0 = acc[mt][nt][half_i * 2 + 0];
                float c1 = acc[mt][nt][half_i * 2 + 1];
                __half h0 = __float2half_rn(c0);
                __half h1 = __float2half_rn(c1);
                if (z == 1) {
                    size_t off = ((size_t)bhI * SEQ + s) * HD + hd;
                    *(uint32_t*)(g_k + off) = pack_f16(h0, h1);
                } else if (z == 2) {
                    __half l0 = __float2half_rn(c0 - __half2float(h0));
                    __half l1 = __float2half_rn(c1 - __half2float(h1));
                    size_t base = ((size_t)bhI * HD + hd) * SEQ + s;
                    g_vth[base] = h0; g_vth[base + SEQ] = h1;
                    g_vtl[base] = l0; g_vtl[base + SEQ] = l1;
                } else {
                    __half l0 = __float2half_rn(c0 - __half2float(h0));
                    __half l1 = __float2half_rn(c1 - __half2float(h1));
                    size_t off = ((size_t)bhI * SEQ + s) * HD + hd;
                    *(uint32_t*)(g_qh + off) = pack_f16(h0, h1);
                    *(uint32_t*)(g_ql + off) = pack_f16(l0, l1);
                }
            }
        }
    }
}

// ---------------------------------------------------------------------------
// Attention: fp16 mma.sync. QK: q split, k plain (2 MMAs). PV: p split,
// v split, drop lo*lo (3 MMAs). Mask u8 in smem, cp.async pipelined.
//   smem: 2 buffers x { K, Vh, Vl [64][72] fp16 (27648 B) + mask 8 KB }.
//   Q (hi/lo, 36864 B) staged across the buffers at startup, then recycled.
// ---------------------------------------------------------------------------
#define ATS 72
#define SM_K  (64 * ATS)             // 4608 elems per region
#define AQ_REG (128 * ATS)           // 9216 elems per Q region
#define AMASK_OFF (3 * SM_K * 2)     // 27648: mask byte offset within buffer
#define ABUF_BYTES (AMASK_OFF + 8192)  // 35840
#define ATTN_SMEM (2 * ABUF_BYTES)   // 71680 (>= 36864 Q staging)

__device__ __forceinline__ void attn_cp_tile(
    uint32_t dstb, const __half* K, const __half* Vh, const __half* Vl,
    const uint8_t* M8, int kt, int tid)
{
    #pragma unroll
    for (int i = tid; i < 512; i += 256) {
        int r = i >> 3, c8 = (i & 7) * 8;
        uint32_t d = dstb + (r * ATS + c8) * 2;
        cp16(d,                K  + (size_t)(kt * 64 + r) * HD + c8);
        cp16(d + SM_K * 2,     Vh + (size_t)r * SEQ + kt * 64 + c8);
        cp16(d + 2 * SM_K * 2, Vl + (size_t)r * SEQ + kt * 64 + c8);
    }
    // mask tile: 128 rows x 64 u8
    #pragma unroll
    for (int i = tid; i < 512; i += 256) {
        int r = i >> 2, c16 = (i & 3) * 16;
        cp16(dstb + AMASK_OFF + r * 64 + c16,
             M8 + (size_t)r * SEQ + kt * 64 + c16);
    }
}

__global__ __launch_bounds__(256, 2) void attn_mma_kernel(float* __restrict__ out)
{
    extern __shared__ __half smd[];
    const uint32_t smb = smem_u32(smd);
    const char* sb = (const char*)smd;

    const int tid = threadIdx.x, w = tid >> 5, lane = tid & 31;
    const int qt = blockIdx.x, bh = blockIdx.y;
    const int b = bh >> 4, h = bh & 15;
    const int gr = lane >> 2, gc2 = (lane & 3) * 2;

    const __half* Qh = g_qh + ((size_t)bh * SEQ + qt * 128) * HD;
    const __half* Ql = g_ql + ((size_t)bh * SEQ + qt * 128) * HD;
    const __half* K  = g_k  + (size_t)bh * SEQ * HD;
    const __half* Vh = g_vth + (size_t)bh * HD * SEQ;
    const __half* Vl = g_vtl + (size_t)bh * HD * SEQ;
    const uint8_t* M8 = g_m8 + (size_t)b * SEQ * SEQ + (size_t)(qt * 128) * SEQ;

    // ---- stage Q (hi/lo) in buffer space, consume to registers ----
    #pragma unroll
    for (int i = tid; i < 1024; i += 256) {
        int r = i >> 3, c8 = (i & 7) * 8;
        cp16(smb + (r * ATS + c8) * 2,          Qh + (size_t)r * HD + c8);
        cp16(smb + (AQ_REG + r * ATS + c8) * 2, Ql + (size_t)r * HD + c8);
    }
    CP_COMMIT();
    CP_WAIT(0);
    __syncthreads();

    uint32_t qh[4][4], ql[4][4];
    {
        const int ar = w * 16 + (lane & 15);
        const int ac = ((lane >> 4) & 1) * 8;
        #pragma unroll
        for (int ks = 0; ks < 4; ks++) {
            ldsm_x4(qh[ks], smb + (ar * ATS + ks * 16 + ac) * 2);
            ldsm_x4(ql[ks], smb + (AQ_REG + ar * ATS + ks * 16 + ac) * 2);
        }
    }
    __syncthreads();   // all warps done reading Q before buffers are recycled

    attn_cp_tile(smb, K, Vh, Vl, M8, 0, tid); CP_COMMIT();

    float ctx[8][4] = {};
    float rs0 = 0.f, rs1 = 0.f;

    const int br = (lane & 7) + ((lane >> 4) << 3);
    const int bc = ((lane >> 3) & 1) * 8;
    const int mrow_off = (w * 16 + gr) * 64 + gc2;

    for (int kt = 0; kt < 16; kt++) {
        CP_WAIT(0);
        __syncthreads();
        if (kt + 1 < 16) {
            attn_cp_tile(smb + ((kt + 1) & 1) * ABUF_BYTES,
                         K, Vh, Vl, M8, kt + 1, tid);
            CP_COMMIT();
        }

        const uint32_t bb = smb + (kt & 1) * ABUF_BYTES;

        // ---- scores = Q K^T (q split, k plain: 2 MMAs) ----
        float acc[8][4] = {};
        #pragma unroll
        for (int ks = 0; ks < 4; ks++) {
            #pragma unroll
            for (int ntp = 0; ntp < 4; ntp++) {
                uint32_t k4[4];
                int off = ((ntp * 16 + br) * ATS + ks * 16 + bc) * 2;
                ldsm_x4(k4, bb + off);
                mma_f16(acc[ntp * 2],     qh[ks], &k4[0]);
                mma_f16(acc[ntp * 2],     ql[ks], &k4[0]);
                mma_f16(acc[ntp * 2 + 1], qh[ks], &k4[2]);
                mma_f16(acc[ntp * 2 + 1], ql[ks], &k4[2]);
            }
        }

        // ---- e = poly_exp(s/8) * mask (u8 from smem); sums; P frags ----
        const char* mp = sb + (kt & 1) * ABUF_BYTES + AMASK_OFF + mrow_off;
        uint32_t ph[4][4], pl[4][4];
        #pragma unroll
        for (int nt = 0; nt < 8; nt++) {
            uint32_t mm01 = *(const uint16_t*)(mp + nt * 8);
            uint32_t mm23 = *(const uint16_t*)(mp + 512 + nt * 8);
            float e0 = fexp8(acc[nt][0]) * (float)(mm01 & 0xFF);
            float e1 = fexp8(acc[nt][1]) * (float)(mm01 >> 8);
            float e2 = fexp8(acc[nt][2]) * (float)(mm23 & 0xFF);
            float e3 = fexp8(acc[nt][3]) * (float)(mm23 >> 8);
            rs0 += e0 + e1;
            rs1 += e2 + e3;
            uint32_t h01 = cvt_f16x2(e0, e1);
            uint32_t h23 = cvt_f16x2(e2, e3);
            float f0, f1, f2, f3;
            unpack_f16x2(h01, f0, f1);
            unpack_f16x2(h23, f2, f3);
            uint32_t l01 = cvt_f16x2(e0 - f0, e1 - f1);
            uint32_t l23 = cvt_f16x2(e2 - f2, e3 - f3);
            int u = nt >> 1, sel = (nt & 1) * 2;
            ph[u][sel]     = h01;
            ph[u][sel + 1] = h23;
            pl[u][sel]     = l01;
            pl[u][sel + 1] = l23;
        }

        // ---- ctx += P V (p split, v split, drop lo*lo: 3 MMAs) ----
        #pragma unroll
        for (int u = 0; u < 4; u++) {
            #pragma unroll
            for (int dtp = 0; dtp < 4; dtp++) {
                uint32_t vh4[4], vl4[4];
                int off = ((dtp * 16 + br) * ATS + u * 16 + bc) * 2;
                ldsm_x4(vh4, bb + SM_K * 2 + off);
                ldsm_x4(vl4, bb + 2 * SM_K * 2 + off);
                mma_f16(ctx[dtp * 2],     ph[u], &vh4[0]);
                mma_f16(ctx[dtp * 2],     ph[u], &vl4[0]);
                mma_f16(ctx[dtp * 2],     pl[u], &vh4[0]);
                mma_f16(ctx[dtp * 2 + 1], ph[u], &vh4[2]);
                mma_f16(ctx[dtp * 2 + 1], ph[u], &vl4[2]);
                mma_f16(ctx[dtp * 2 + 1], pl[u], &vh4[2]);
            }
        }
    }

    // ---- denominators + output ----
    rs0 += __shfl_xor_sync(0xffffffffu, rs0, 1);
    rs0 += __shfl_xor_sync(0xffffffffu, rs0, 2);
    rs1 += __shfl_xor_sync(0xffffffffu, rs1, 1);
    rs1 += __shfl_xor_sync(0xffffffffu, rs1, 2);
    float inv0 = 1.0f / (rs0 + 1e-8f);
    float inv1 = 1.0f / (rs1 + 1e-8f);

    const int s0 = qt * 128 + w * 16 + gr;
    float* O = out + (((size_t)b * SEQ + s0) * NH + h) * HD + gc2;
    #pragma unroll
    for (int dt = 0; dt < 8; dt++) {
        *(float2*)&O[dt * 8] =
            make_float2(ctx[dt][0] * inv0, ctx[dt][1] * inv0);
        *(float2*)&O[(size_t)8 * NH * HD + dt * 8] =
            make_float2(ctx[dt][2] * inv1, ctx[dt][3] * inv1);
    }
}

// ---------------------------------------------------------------------------
extern "C" void kernel_launch(void* const* d_in, const int* in_sizes, int n_in,
                              void* d_out, int out_size)
{
    const float* x    = (const float*)d_in[0];
    const float* mask = (const float*)d_in[1];
    const float* Wq   = (const float*)d_in[2];
    const float* Wk   = (const float*)d_in[3];
    const float* Wv   = (const float*)d_in[4];
    float* out = (float*)d_out;

    static int init = 0;
    if (!init) {
        cudaFuncSetAttribute(qkv_mma_kernel,
            cudaFuncAttributeMaxDynamicSharedMemorySize, QKV_SMEM);
        cudaFuncSetAttribute(attn_mma_kernel,
            cudaFuncAttributeMaxDynamicSharedMemorySize, ATTN_SMEM);
        init = 1;
    }

    convert_x_kernel<<<BATCH * SEQ, 256>>>(x);
    convert_mask_kernel<<<BATCH * SEQ * SEQ / 1024, 256>>>(mask);
    convert_wt_kernel<<<dim3(32, 32, 3), dim3(32, 8)>>>(Wq, Wk, Wv);
    qkv_mma_kernel<<<dim3(64, 8, 3), 256, QKV_SMEM>>>();
    attn_mma_kernel<<<dim3(8, 128), 256, ATTN_SMEM>>>(out);
}

// round 10
// speedup vs baseline: 4.6170x; 1.2515x over previous
#include <cuda_runtime.h>
#include <cuda_fp16.h>
#include <cstdint>

#define BATCH 8
#define SEQ   1024
#define DIM   1024
#define NH    16
#define HD    64

// split-fp16 operands for MMA projections
__device__ __half g_xh[BATCH*SEQ*DIM];     // x hi   [m][k]
__device__ __half g_xl[BATCH*SEQ*DIM];     // x lo
__device__ __half g_wt[3*DIM*DIM];         // W^T plain fp16 [n][k]

// attention operands (written by QKV GEMM epilogue)
__device__ __half g_qh [BATCH*NH*SEQ*HD];  // Q hi  [bh][s][hd]
__device__ __half g_ql [BATCH*NH*SEQ*HD];  // Q lo
__device__ __half g_k  [BATCH*NH*SEQ*HD];  // K plain [bh][s][hd]
__device__ __half g_vt [BATCH*NH*HD*SEQ];  // V^T plain [bh][hd][s]

// binary mask packed to u8
__device__ uint8_t g_m8[BATCH*SEQ*SEQ];

// ---------------------------------------------------------------------------
// helpers
// ---------------------------------------------------------------------------
__device__ __forceinline__ uint32_t smem_u32(const void* p) {
    uint32_t a;
    asm("{ .reg .u64 t; cvta.to.shared.u64 t, %1; cvt.u32.u64 %0, t; }"
        : "=r"(a) : "l"(p));
    return a;
}
__device__ __forceinline__ void ldsm_x4(uint32_t a[4], uint32_t addr) {
    asm volatile("ldmatrix.sync.aligned.m8n8.x4.shared.b16 {%0,%1,%2,%3}, [%4];"
                 : "=r"(a[0]), "=r"(a[1]), "=r"(a[2]), "=r"(a[3]) : "r"(addr));
}
__device__ __forceinline__ void ldsm_x2(uint32_t b[2], uint32_t addr) {
    asm volatile("ldmatrix.sync.aligned.m8n8.x2.shared.b16 {%0,%1}, [%2];"
                 : "=r"(b[0]), "=r"(b[1]) : "r"(addr));
}
__device__ __forceinline__ void mma_f16(float c[4], const uint32_t a[4],
                                        const uint32_t b[2]) {
    asm volatile(
        "mma.sync.aligned.m16n8k16.row.col.f32.f16.f16.f32 "
        "{%0,%1,%2,%3}, {%4,%5,%6,%7}, {%8,%9}, {%0,%1,%2,%3};"
        : "+f"(c[0]), "+f"(c[1]), "+f"(c[2]), "+f"(c[3])
        : "r"(a[0]), "r"(a[1]), "r"(a[2]), "r"(a[3]), "r"(b[0]), "r"(b[1]));
}
__device__ __forceinline__ uint32_t pack_f16(__half a, __half b) {
    __half2 p; p.x = a; p.y = b;
    return *(uint32_t*)&p;
}
// packed {lo, hi} f16x2 from two floats
__device__ __forceinline__ uint32_t cvt_f16x2(float lo, float hi) {
    uint32_t r;
    asm("cvt.rn.f16x2.f32 %0, %1, %2;" : "=r"(r) : "f"(hi), "f"(lo));
    return r;
}
__device__ __forceinline__ void cp16(uint32_t dst, const void* src) {
    asm volatile("cp.async.cg.shared.global [%0], [%1], 16;"
                 :: "r"(dst), "l"(src));
}
#define CP_COMMIT() asm volatile("cp.async.commit_group;" ::: "memory")
#define CP_WAIT(n)  asm volatile("cp.async.wait_group %0;" :: "n"(n) : "memory")

// exp(s/8) via exp2 poly: t = s*log2e/8; magic round; degree-5 Taylor on [-.5,.5]
__device__ __forceinline__ float fexp8(float s) {
    float t = s * 0.18033688011112042f;          // log2(e)/8
    float k = t + 12582912.0f;                   // 1.5*2^23 magic round
    float j = k - 12582912.0f;
    float f = t - j;
    float p = 1.3333558147e-3f;
    p = fmaf(p, f, 9.6181291076e-3f);
    p = fmaf(p, f, 5.5504108665e-2f);
    p = fmaf(p, f, 2.4022650696e-1f);
    p = fmaf(p, f, 6.9314718056e-1f);
    p = fmaf(p, f, 1.0f);
    int ib = __float_as_int(k) - 0x4B400000;
    float scale = __int_as_float((ib + 127) << 23);
    return p * scale;
}

// ---------------------------------------------------------------------------
// Preprocess: split x -> (hi, lo) fp16
// ---------------------------------------------------------------------------
__global__ __launch_bounds__(256) void convert_x_kernel(const float* __restrict__ x) {
    int i = (blockIdx.x * 256 + threadIdx.x) * 4;
    float4 v = *(const float4*)(x + i);
    __half h0 = __float2half_rn(v.x), h1 = __float2half_rn(v.y);
    __half h2 = __float2half_rn(v.z), h3 = __float2half_rn(v.w);
    *(uint32_t*)(g_xh + i)     = pack_f16(h0, h1);
    *(uint32_t*)(g_xh + i + 2) = pack_f16(h2, h3);
    *(uint32_t*)(g_xl + i)     = pack_f16(
        __float2half_rn(v.x - __half2float(h0)),
        __float2half_rn(v.y - __half2float(h1)));
    *(uint32_t*)(g_xl + i + 2) = pack_f16(
        __float2half_rn(v.z - __half2float(h2)),
        __float2half_rn(v.w - __half2float(h3)));
}

// Preprocess: mask f32 (0/1) -> u8
__global__ __launch_bounds__(256) void convert_mask_kernel(const float* __restrict__ m) {
    int i = (blockIdx.x * 256 + threadIdx.x) * 4;
    float4 v = *(const float4*)(m + i);
    uint32_t p = (uint32_t)(v.x != 0.0f)
               | ((uint32_t)(v.y != 0.0f) << 8)
               | ((uint32_t)(v.z != 0.0f) << 16)
               | ((uint32_t)(v.w != 0.0f) << 24);
    *(uint32_t*)(g_m8 + i) = p;
}

// Preprocess: W[k][n] -> Wt[n][k] plain fp16
__global__ __launch_bounds__(256) void convert_wt_kernel(
    const float* __restrict__ Wq, const float* __restrict__ Wk,
    const float* __restrict__ Wv)
{
    __shared__ float t[32][33];
    const int z = blockIdx.z;
    const float* __restrict__ W = (z == 0) ? Wq : (z == 1 ? Wk : Wv);
    const int n0 = blockIdx.x * 32, k0 = blockIdx.y * 32;
    const int tx = threadIdx.x, ty = threadIdx.y;   // block (32, 8)

    #pragma unroll
    for (int i = ty; i < 32; i += 8)
        t[i][tx] = W[(size_t)(k0 + i) * DIM + n0 + tx];
    __syncthreads();

    __half* wt = g_wt + (size_t)z * DIM * DIM;
    #pragma unroll
    for (int i = ty; i < 32; i += 8)
        wt[(size_t)(n0 + i) * DIM + k0 + tx] = __float2half_rn(t[tx][i]);
}

// ---------------------------------------------------------------------------
// QKV projection GEMM: fp16, x split hi/lo, W plain -> 2 MMAs per tile.
//   128x128 tile, 8 warps (2x4), warp tile 64x32, BK=64 (16 iters).
//   smem: 2 bufs x 3 regions (xh, xl, W) x 128 x 72 fp16 = 110592 B.
// ---------------------------------------------------------------------------
#define BK 64
#define LDS 72
#define QREG (128 * LDS)          // 9216 elems per region
#define QBUF (3 * QREG)           // 27648 elems per buffer
#define QKV_SMEM (2 * QBUF * 2)   // 110592 bytes

__device__ __forceinline__ void qkv_cp_blk(
    uint32_t dstb, const __half* const* srcs, int k0, int tid)
{
    #pragma unroll
    for (int t = 0; t < 3; t++) {
        const __half* s = srcs[t] + k0;
        #pragma unroll
        for (int i = tid; i < 1024; i += 256) {
            int r = i >> 3, c8 = (i & 7) * 8;
            cp16(dstb + (t * QREG + r * LDS + c8) * 2,
                 s + (size_t)r * DIM + c8);
        }
    }
}

__global__ __launch_bounds__(256, 2) void qkv_mma_kernel()
{
    extern __shared__ __half smd[];
    const uint32_t smb = smem_u32(smd);

    const int tid  = threadIdx.x;
    const int w    = tid >> 5, lane = tid & 31;
    const int wm   = w >> 2, wn = w & 3;
    const int m0   = blockIdx.x * 128;
    const int n0   = blockIdx.y * 128;
    const int z    = blockIdx.z;

    const __half* srcs[3] = {
        g_xh + (size_t)m0 * DIM,
        g_xl + (size_t)m0 * DIM,
        g_wt + (size_t)z * DIM * DIM + (size_t)n0 * DIM
    };

    const int a_row = lane & 15, a_kh = (lane >> 4) * 8;
    const int b_row = lane & 7,  b_kh = ((lane >> 3) & 1) * 8;

    float acc[4][4][4] = {};

    qkv_cp_blk(smb, srcs, 0, tid); CP_COMMIT();

    const int NB = DIM / BK;   // 16
    for (int blk = 0; blk < NB; blk++) {
        CP_WAIT(0);
        __syncthreads();
        if (blk + 1 < NB) {
            qkv_cp_blk(smb + ((blk + 1) & 1) * QBUF * 2, srcs,
                       (blk + 1) * BK, tid);
            CP_COMMIT();
        }

        const uint32_t bb = smb + (blk & 1) * QBUF * 2;
        #pragma unroll
        for (int kk = 0; kk < BK; kk += 16) {
            uint32_t ah[4][4], al[4][4];
            #pragma unroll
            for (int mt = 0; mt < 4; mt++) {
                int roff = ((wm * 64 + mt * 16 + a_row) * LDS + kk + a_kh) * 2;
                ldsm_x4(ah[mt], bb + roff);
                ldsm_x4(al[mt], bb + QREG * 2 + roff);
            }
            uint32_t bw[4][2];
            #pragma unroll
            for (int nt = 0; nt < 4; nt++) {
                int roff = ((wn * 32 + nt * 8 + b_row) * LDS + kk + b_kh) * 2;
                ldsm_x2(bw[nt], bb + 2 * QREG * 2 + roff);
            }
            #pragma unroll
            for (int mt = 0; mt < 4; mt++)
                #pragma unroll
                for (int nt = 0; nt < 4; nt++) {
                    mma_f16(acc[mt][nt], ah[mt], bw[nt]);
                    mma_f16(acc[mt][nt], al[mt], bw[nt]);
                }
        }
    }

    // epilogue -> fp16 (q hi/lo, k plain, v^T plain)
    const int em = lane >> 2, en = (lane & 3) * 2;
    #pragma unroll
    for (int mt = 0; mt < 4; mt++) {
        #pragma unroll
        for (int nt = 0; nt < 4; nt++) {
            int mg0 = m0 + wm * 64 + mt * 16 + em;
            int ng  = n0 + wn * 32 + nt * 8 + en;
            int h = ng >> 6, hd = ng & 63;
            #pragma unroll
            for (int half_i = 0; half_i < 2; half_i++) {
                int mg = mg0 + half_i * 8;
                int b = mg >> 10, s = mg & 1023;
                int bhI = b * NH + h;
                float c0 = acc[mt][nt][half_i * 2 + 0];
                float c1 = acc[mt][nt][half_i * 2 + 1];
                __half h0 = __float2half_rn(c0);
                __half h1 = __float2half_rn(c1);
                if (z == 1) {
                    size_t off = ((size_t)bhI * SEQ + s) * HD + hd;
                    *(uint32_t*)(g_k + off) = pack_f16(h0, h1);
                } else if (z == 2) {
                    size_t base = ((size_t)bhI * HD + hd) * SEQ + s;
                    g_vt[base] = h0; g_vt[base + SEQ] = h1;
                } else {
                    __half l0 = __float2half_rn(c0 - __half2float(h0));
                    __half l1 = __float2half_rn(c1 - __half2float(h1));
                    size_t off = ((size_t)bhI * SEQ + s) * HD + hd;
                    *(uint32_t*)(g_qh + off) = pack_f16(h0, h1);
                    *(uint32_t*)(g_ql + off) = pack_f16(l0, l1);
                }
            }
        }
    }
}

// ---------------------------------------------------------------------------
// Attention: fp16 mma.sync. QK: q split, k plain (2 MMAs). PV: p plain,
// v plain (1 MMA). Mask u8 in smem, cp.async pipelined.
//   smem: 2 buffers x { K, V [64][72] fp16 (18432 B) + mask 8 KB } = 53248 B.
//   Q (hi/lo, 36864 B) staged across the buffers at startup, then recycled.
// ---------------------------------------------------------------------------
#define ATS 72
#define SM_K  (64 * ATS)             // 4608 elems per region
#define AQ_REG (128 * ATS)           // 9216 elems per Q region
#define AMASK_OFF (2 * SM_K * 2)     // 18432: mask byte offset within buffer
#define ABUF_BYTES (AMASK_OFF + 8192)  // 26624
#define ATTN_SMEM (2 * ABUF_BYTES)   // 53248 (>= 36864 Q staging)

__device__ __forceinline__ void attn_cp_tile(
    uint32_t dstb, const __half* K, const __half* V,
    const uint8_t* M8, int kt, int tid)
{
    #pragma unroll
    for (int i = tid; i < 512; i += 256) {
        int r = i >> 3, c8 = (i & 7) * 8;
        uint32_t d = dstb + (r * ATS + c8) * 2;
        cp16(d,            K + (size_t)(kt * 64 + r) * HD + c8);
        cp16(d + SM_K * 2, V + (size_t)r * SEQ + kt * 64 + c8);
    }
    // mask tile: 128 rows x 64 u8
    #pragma unroll
    for (int i = tid; i < 512; i += 256) {
        int r = i >> 2, c16 = (i & 3) * 16;
        cp16(dstb + AMASK_OFF + r * 64 + c16,
             M8 + (size_t)r * SEQ + kt * 64 + c16);
    }
}

__global__ __launch_bounds__(256, 2) void attn_mma_kernel(float* __restrict__ out)
{
    extern __shared__ __half smd[];
    const uint32_t smb = smem_u32(smd);
    const char* sb = (const char*)smd;

    const int tid = threadIdx.x, w = tid >> 5, lane = tid & 31;
    const int qt = blockIdx.x, bh = blockIdx.y;
    const int b = bh >> 4, h = bh & 15;
    const int gr = lane >> 2, gc2 = (lane & 3) * 2;

    const __half* Qh = g_qh + ((size_t)bh * SEQ + qt * 128) * HD;
    const __half* Ql = g_ql + ((size_t)bh * SEQ + qt * 128) * HD;
    const __half* K  = g_k  + (size_t)bh * SEQ * HD;
    const __half* V  = g_vt + (size_t)bh * HD * SEQ;
    const uint8_t* M8 = g_m8 + (size_t)b * SEQ * SEQ + (size_t)(qt * 128) * SEQ;

    // ---- stage Q (hi/lo) in buffer space, consume to registers ----
    #pragma unroll
    for (int i = tid; i < 1024; i += 256) {
        int r = i >> 3, c8 = (i & 7) * 8;
        cp16(smb + (r * ATS + c8) * 2,          Qh + (size_t)r * HD + c8);
        cp16(smb + (AQ_REG + r * ATS + c8) * 2, Ql + (size_t)r * HD + c8);
    }
    CP_COMMIT();
    CP_WAIT(0);
    __syncthreads();

    uint32_t qh[4][4], ql[4][4];
    {
        const int ar = w * 16 + (lane & 15);
        const int ac = ((lane >> 4) & 1) * 8;
        #pragma unroll
        for (int ks = 0; ks < 4; ks++) {
            ldsm_x4(qh[ks], smb + (ar * ATS + ks * 16 + ac) * 2);
            ldsm_x4(ql[ks], smb + (AQ_REG + ar * ATS + ks * 16 + ac) * 2);
        }
    }
    __syncthreads();   // all warps done reading Q before buffers are recycled

    attn_cp_tile(smb, K, V, M8, 0, tid); CP_COMMIT();

    float ctx[8][4] = {};
    float rs0 = 0.f, rs1 = 0.f;

    const int br = (lane & 7) + ((lane >> 4) << 3);
    const int bc = ((lane >> 3) & 1) * 8;
    const int mrow_off = (w * 16 + gr) * 64 + gc2;

    for (int kt = 0; kt < 16; kt++) {
        CP_WAIT(0);
        __syncthreads();
        if (kt + 1 < 16) {
            attn_cp_tile(smb + ((kt + 1) & 1) * ABUF_BYTES,
                         K, V, M8, kt + 1, tid);
            CP_COMMIT();
        }

        const uint32_t bb = smb + (kt & 1) * ABUF_BYTES;

        // ---- scores = Q K^T (q split, k plain: 2 MMAs) ----
        float acc[8][4] = {};
        #pragma unroll
        for (int ks = 0; ks < 4; ks++) {
            #pragma unroll
            for (int ntp = 0; ntp < 4; ntp++) {
                uint32_t k4[4];
                int off = ((ntp * 16 + br) * ATS + ks * 16 + bc) * 2;
                ldsm_x4(k4, bb + off);
                mma_f16(acc[ntp * 2],     qh[ks], &k4[0]);
                mma_f16(acc[ntp * 2],     ql[ks], &k4[0]);
                mma_f16(acc[ntp * 2 + 1], qh[ks], &k4[2]);
                mma_f16(acc[ntp * 2 + 1], ql[ks], &k4[2]);
            }
        }

        // ---- e = poly_exp(s/8) * mask (u8 from smem); sums; P frags ----
        const char* mp = sb + (kt & 1) * ABUF_BYTES + AMASK_OFF + mrow_off;
        uint32_t ph[4][4];
        #pragma unroll
        for (int nt = 0; nt < 8; nt++) {
            uint32_t mm01 = *(const uint16_t*)(mp + nt * 8);
            uint32_t mm23 = *(const uint16_t*)(mp + 512 + nt * 8);
            float e0 = fexp8(acc[nt][0]) * (float)(mm01 & 0xFF);
            float e1 = fexp8(acc[nt][1]) * (float)(mm01 >> 8);
            float e2 = fexp8(acc[nt][2]) * (float)(mm23 & 0xFF);
            float e3 = fexp8(acc[nt][3]) * (float)(mm23 >> 8);
            rs0 += e0 + e1;
            rs1 += e2 + e3;
            int u = nt >> 1, sel = (nt & 1) * 2;
            ph[u][sel]     = cvt_f16x2(e0, e1);
            ph[u][sel + 1] = cvt_f16x2(e2, e3);
        }

        // ---- ctx += P V (p plain, v plain: 1 MMA) ----
        #pragma unroll
        for (int u = 0; u < 4; u++) {
            #pragma unroll
            for (int dtp = 0; dtp < 4; dtp++) {
                uint32_t v4[4];
                int off = ((dtp * 16 + br) * ATS + u * 16 + bc) * 2;
                ldsm_x4(v4, bb + SM_K * 2 + off);
                mma_f16(ctx[dtp * 2],     ph[u], &v4[0]);
                mma_f16(ctx[dtp * 2 + 1], ph[u], &v4[2]);
            }
        }
    }

    // ---- denominators + output ----
    rs0 += __shfl_xor_sync(0xffffffffu, rs0, 1);
    rs0 += __shfl_xor_sync(0xffffffffu, rs0, 2);
    rs1 += __shfl_xor_sync(0xffffffffu, rs1, 1);
    rs1 += __shfl_xor_sync(0xffffffffu, rs1, 2);
    float inv0 = 1.0f / (rs0 + 1e-8f);
    float inv1 = 1.0f / (rs1 + 1e-8f);

    const int s0 = qt * 128 + w * 16 + gr;
    float* O = out + (((size_t)b * SEQ + s0) * NH + h) * HD + gc2;
    #pragma unroll
    for (int dt = 0; dt < 8; dt++) {
        *(float2*)&O[dt * 8] =
            make_float2(ctx[dt][0] * inv0, ctx[dt][1] * inv0);
        *(float2*)&O[(size_t)8 * NH * HD + dt * 8] =
            make_float2(ctx[dt][2] * inv1, ctx[dt][3] * inv1);
    }
}

// ---------------------------------------------------------------------------
extern "C" void kernel_launch(void* const* d_in, const int* in_sizes, int n_in,
                              void* d_out, int out_size)
{
    const float* x    = (const float*)d_in[0];
    const float* mask = (const float*)d_in[1];
    const float* Wq   = (const float*)d_in[2];
    const float* Wk   = (const float*)d_in[3];
    const float* Wv   = (const float*)d_in[4];
    float* out = (float*)d_out;

    static int init = 0;
    if (!init) {
        cudaFuncSetAttribute(qkv_mma_kernel,
            cudaFuncAttributeMaxDynamicSharedMemorySize, QKV_SMEM);
        cudaFuncSetAttribute(attn_mma_kernel,
            cudaFuncAttributeMaxDynamicSharedMemorySize, ATTN_SMEM);
        init = 1;
    }

    convert_x_kernel<<<BATCH * SEQ, 256>>>(x);
    convert_mask_kernel<<<BATCH * SEQ * SEQ / 1024, 256>>>(mask);
    convert_wt_kernel<<<dim3(32, 32, 3), dim3(32, 8)>>>(Wq, Wk, Wv);
    qkv_mma_kernel<<<dim3(64, 8, 3), 256, QKV_SMEM>>>();
    attn_mma_kernel<<<dim3(8, 128), 256, ATTN_SMEM>>>(out);
}

// round 11
// speedup vs baseline: 6.4178x; 1.3900x over previous
#include <cuda_runtime.h>
#include <cuda_fp16.h>
#include <cstdint>

#define BATCH 8
#define SEQ   1024
#define DIM   1024
#define NH    16
#define HD    64

// plain fp16 operands
__device__ __half g_x [BATCH*SEQ*DIM];     // x   [m][k]
__device__ __half g_wt[3*DIM*DIM];         // W^T [n][k]

// attention operands (written by QKV GEMM epilogue)
__device__ __half g_q [BATCH*NH*SEQ*HD];   // Q  [bh][s][hd]
__device__ __half g_k [BATCH*NH*SEQ*HD];   // K  [bh][s][hd]
__device__ __half g_vt[BATCH*NH*HD*SEQ];   // V^T [bh][hd][s]

// binary mask packed to u8
__device__ uint8_t g_m8[BATCH*SEQ*SEQ];

// ---------------------------------------------------------------------------
// helpers
// ---------------------------------------------------------------------------
__device__ __forceinline__ uint32_t smem_u32(const void* p) {
    uint32_t a;
    asm("{ .reg .u64 t; cvta.to.shared.u64 t, %1; cvt.u32.u64 %0, t; }"
        : "=r"(a) : "l"(p));
    return a;
}
__device__ __forceinline__ void ldsm_x4(uint32_t a[4], uint32_t addr) {
    asm volatile("ldmatrix.sync.aligned.m8n8.x4.shared.b16 {%0,%1,%2,%3}, [%4];"
                 : "=r"(a[0]), "=r"(a[1]), "=r"(a[2]), "=r"(a[3]) : "r"(addr));
}
__device__ __forceinline__ void ldsm_x2(uint32_t b[2], uint32_t addr) {
    asm volatile("ldmatrix.sync.aligned.m8n8.x2.shared.b16 {%0,%1}, [%2];"
                 : "=r"(b[0]), "=r"(b[1]) : "r"(addr));
}
__device__ __forceinline__ void mma_f16(float c[4], const uint32_t a[4],
                                        const uint32_t b[2]) {
    asm volatile(
        "mma.sync.aligned.m16n8k16.row.col.f32.f16.f16.f32 "
        "{%0,%1,%2,%3}, {%4,%5,%6,%7}, {%8,%9}, {%0,%1,%2,%3};"
        : "+f"(c[0]), "+f"(c[1]), "+f"(c[2]), "+f"(c[3])
        : "r"(a[0]), "r"(a[1]), "r"(a[2]), "r"(a[3]), "r"(b[0]), "r"(b[1]));
}
__device__ __forceinline__ uint32_t pack_f16(__half a, __half b) {
    __half2 p; p.x = a; p.y = b;
    return *(uint32_t*)&p;
}
// packed {lo, hi} f16x2 from two floats
__device__ __forceinline__ uint32_t cvt_f16x2(float lo, float hi) {
    uint32_t r;
    asm("cvt.rn.f16x2.f32 %0, %1, %2;" : "=r"(r) : "f"(hi), "f"(lo));
    return r;
}
__device__ __forceinline__ void cp16(uint32_t dst, const void* src) {
    asm volatile("cp.async.cg.shared.global [%0], [%1], 16;"
                 :: "r"(dst), "l"(src));
}
#define CP_COMMIT() asm volatile("cp.async.commit_group;" ::: "memory")
#define CP_WAIT(n)  asm volatile("cp.async.wait_group %0;" :: "n"(n) : "memory")

// exp(s/8) via exp2 poly: t = s*log2e/8; magic round; degree-5 Taylor on [-.5,.5]
__device__ __forceinline__ float fexp8(float s) {
    float t = s * 0.18033688011112042f;          // log2(e)/8
    float k = t + 12582912.0f;                   // 1.5*2^23 magic round
    float j = k - 12582912.0f;
    float f = t - j;
    float p = 1.3333558147e-3f;
    p = fmaf(p, f, 9.6181291076e-3f);
    p = fmaf(p, f, 5.5504108665e-2f);
    p = fmaf(p, f, 2.4022650696e-1f);
    p = fmaf(p, f, 6.9314718056e-1f);
    p = fmaf(p, f, 1.0f);
    int ib = __float_as_int(k) - 0x4B400000;
    float scale = __int_as_float((ib + 127) << 23);
    return p * scale;
}

// ---------------------------------------------------------------------------
// Preprocess: x -> fp16
// ---------------------------------------------------------------------------
__global__ __launch_bounds__(256) void convert_x_kernel(const float* __restrict__ x) {
    int i = (blockIdx.x * 256 + threadIdx.x) * 4;
    float4 v = *(const float4*)(x + i);
    *(uint32_t*)(g_x + i)     = pack_f16(__float2half_rn(v.x), __float2half_rn(v.y));
    *(uint32_t*)(g_x + i + 2) = pack_f16(__float2half_rn(v.z), __float2half_rn(v.w));
}

// Preprocess: mask f32 (0/1) -> u8
__global__ __launch_bounds__(256) void convert_mask_kernel(const float* __restrict__ m) {
    int i = (blockIdx.x * 256 + threadIdx.x) * 4;
    float4 v = *(const float4*)(m + i);
    uint32_t p = (uint32_t)(v.x != 0.0f)
               | ((uint32_t)(v.y != 0.0f) << 8)
               | ((uint32_t)(v.z != 0.0f) << 16)
               | ((uint32_t)(v.w != 0.0f) << 24);
    *(uint32_t*)(g_m8 + i) = p;
}

// Preprocess: W[k][n] -> Wt[n][k] fp16
__global__ __launch_bounds__(256) void convert_wt_kernel(
    const float* __restrict__ Wq, const float* __restrict__ Wk,
    const float* __restrict__ Wv)
{
    __shared__ float t[32][33];
    const int z = blockIdx.z;
    const float* __restrict__ W = (z == 0) ? Wq : (z == 1 ? Wk : Wv);
    const int n0 = blockIdx.x * 32, k0 = blockIdx.y * 32;
    const int tx = threadIdx.x, ty = threadIdx.y;   // block (32, 8)

    #pragma unroll
    for (int i = ty; i < 32; i += 8)
        t[i][tx] = W[(size_t)(k0 + i) * DIM + n0 + tx];
    __syncthreads();

    __half* wt = g_wt + (size_t)z * DIM * DIM;
    #pragma unroll
    for (int i = ty; i < 32; i += 8)
        wt[(size_t)(n0 + i) * DIM + k0 + tx] = __float2half_rn(t[tx][i]);
}

// ---------------------------------------------------------------------------
// QKV projection GEMM: plain fp16, 1 MMA per tile.
//   128x128 tile, 8 warps (2x4), warp tile 64x32, BK=64 (16 iters).
//   smem: 2 bufs x 2 regions (x, W) x 128 x 72 fp16 = 73728 B.
// ---------------------------------------------------------------------------
#define BK 64
#define LDS 72
#define QREG (128 * LDS)          // 9216 elems per region
#define QBUF (2 * QREG)           // 18432 elems per buffer
#define QKV_SMEM (2 * QBUF * 2)   // 73728 bytes

__device__ __forceinline__ void qkv_cp_blk(
    uint32_t dstb, const __half* const* srcs, int k0, int tid)
{
    #pragma unroll
    for (int t = 0; t < 2; t++) {
        const __half* s = srcs[t] + k0;
        #pragma unroll
        for (int i = tid; i < 1024; i += 256) {
            int r = i >> 3, c8 = (i & 7) * 8;
            cp16(dstb + (t * QREG + r * LDS + c8) * 2,
                 s + (size_t)r * DIM + c8);
        }
    }
}

__global__ __launch_bounds__(256, 2) void qkv_mma_kernel()
{
    extern __shared__ __half smd[];
    const uint32_t smb = smem_u32(smd);

    const int tid  = threadIdx.x;
    const int w    = tid >> 5, lane = tid & 31;
    const int wm   = w >> 2, wn = w & 3;
    const int m0   = blockIdx.x * 128;
    const int n0   = blockIdx.y * 128;
    const int z    = blockIdx.z;

    const __half* srcs[2] = {
        g_x + (size_t)m0 * DIM,
        g_wt + (size_t)z * DIM * DIM + (size_t)n0 * DIM
    };

    const int a_row = lane & 15, a_kh = (lane >> 4) * 8;
    const int b_row = lane & 7,  b_kh = ((lane >> 3) & 1) * 8;

    float acc[4][4][4] = {};

    qkv_cp_blk(smb, srcs, 0, tid); CP_COMMIT();

    const int NB = DIM / BK;   // 16
    for (int blk = 0; blk < NB; blk++) {
        CP_WAIT(0);
        __syncthreads();
        if (blk + 1 < NB) {
            qkv_cp_blk(smb + ((blk + 1) & 1) * QBUF * 2, srcs,
                       (blk + 1) * BK, tid);
            CP_COMMIT();
        }

        const uint32_t bb = smb + (blk & 1) * QBUF * 2;
        #pragma unroll
        for (int kk = 0; kk < BK; kk += 16) {
            uint32_t ax[4][4];
            #pragma unroll
            for (int mt = 0; mt < 4; mt++) {
                int roff = ((wm * 64 + mt * 16 + a_row) * LDS + kk + a_kh) * 2;
                ldsm_x4(ax[mt], bb + roff);
            }
            uint32_t bw[4][2];
            #pragma unroll
            for (int nt = 0; nt < 4; nt++) {
                int roff = ((wn * 32 + nt * 8 + b_row) * LDS + kk + b_kh) * 2;
                ldsm_x2(bw[nt], bb + QREG * 2 + roff);
            }
            #pragma unroll
            for (int mt = 0; mt < 4; mt++)
                #pragma unroll
                for (int nt = 0; nt < 4; nt++)
                    mma_f16(acc[mt][nt], ax[mt], bw[nt]);
        }
    }

    // epilogue -> fp16 (q, k plain row-major; v^T plain)
    const int em = lane >> 2, en = (lane & 3) * 2;
    #pragma unroll
    for (int mt = 0; mt < 4; mt++) {
        #pragma unroll
        for (int nt = 0; nt < 4; nt++) {
            int mg0 = m0 + wm * 64 + mt * 16 + em;
            int ng  = n0 + wn * 32 + nt * 8 + en;
            int h = ng >> 6, hd = ng & 63;
            #pragma unroll
            for (int half_i = 0; half_i < 2; half_i++) {
                int mg = mg0 + half_i * 8;
                int b = mg >> 10, s = mg & 1023;
                int bhI = b * NH + h;
                float c0 = acc[mt][nt][half_i * 2 + 0];
                float c1 = acc[mt][nt][half_i * 2 + 1];
                __half h0 = __float2half_rn(c0);
                __half h1 = __float2half_rn(c1);
                if (z == 2) {
                    size_t base = ((size_t)bhI * HD + hd) * SEQ + s;
                    g_vt[base] = h0; g_vt[base + SEQ] = h1;
                } else {
                    size_t off = ((size_t)bhI * SEQ + s) * HD + hd;
                    *(uint32_t*)((z ? g_k : g_q) + off) = pack_f16(h0, h1);
                }
            }
        }
    }
}

// ---------------------------------------------------------------------------
// Attention: plain fp16 mma.sync, 1 MMA for QK and 1 for PV.
//   Mask u8 in smem, cp.async pipelined.
//   smem: 2 buffers x { K, V [64][72] fp16 (18432 B) + mask 8 KB } = 53248 B.
//   Q (plain, 18432 B) staged in buffer 0 at startup, then recycled.
// ---------------------------------------------------------------------------
#define ATS 72
#define SM_K  (64 * ATS)             // 4608 elems per region
#define AMASK_OFF (2 * SM_K * 2)     // 18432: mask byte offset within buffer
#define ABUF_BYTES (AMASK_OFF + 8192)  // 26624
#define ATTN_SMEM (2 * ABUF_BYTES)   // 53248

__device__ __forceinline__ void attn_cp_tile(
    uint32_t dstb, const __half* K, const __half* V,
    const uint8_t* M8, int kt, int tid)
{
    #pragma unroll
    for (int i = tid; i < 512; i += 256) {
        int r = i >> 3, c8 = (i & 7) * 8;
        uint32_t d = dstb + (r * ATS + c8) * 2;
        cp16(d,            K + (size_t)(kt * 64 + r) * HD + c8);
        cp16(d + SM_K * 2, V + (size_t)r * SEQ + kt * 64 + c8);
    }
    // mask tile: 128 rows x 64 u8
    #pragma unroll
    for (int i = tid; i < 512; i += 256) {
        int r = i >> 2, c16 = (i & 3) * 16;
        cp16(dstb + AMASK_OFF + r * 64 + c16,
             M8 + (size_t)r * SEQ + kt * 64 + c16);
    }
}

__global__ __launch_bounds__(256, 2) void attn_mma_kernel(float* __restrict__ out)
{
    extern __shared__ __half smd[];
    const uint32_t smb = smem_u32(smd);
    const char* sb = (const char*)smd;

    const int tid = threadIdx.x, w = tid >> 5, lane = tid & 31;
    const int qt = blockIdx.x, bh = blockIdx.y;
    const int b = bh >> 4, h = bh & 15;
    const int gr = lane >> 2, gc2 = (lane & 3) * 2;

    const __half* Q  = g_q  + ((size_t)bh * SEQ + qt * 128) * HD;
    const __half* K  = g_k  + (size_t)bh * SEQ * HD;
    const __half* V  = g_vt + (size_t)bh * HD * SEQ;
    const uint8_t* M8 = g_m8 + (size_t)b * SEQ * SEQ + (size_t)(qt * 128) * SEQ;

    // ---- stage Q (plain) in buffer space, consume to registers ----
    #pragma unroll
    for (int i = tid; i < 1024; i += 256) {
        int r = i >> 3, c8 = (i & 7) * 8;
        cp16(smb + (r * ATS + c8) * 2, Q + (size_t)r * HD + c8);
    }
    CP_COMMIT();
    CP_WAIT(0);
    __syncthreads();

    uint32_t qf[4][4];
    {
        const int ar = w * 16 + (lane & 15);
        const int ac = ((lane >> 4) & 1) * 8;
        #pragma unroll
        for (int ks = 0; ks < 4; ks++)
            ldsm_x4(qf[ks], smb + (ar * ATS + ks * 16 + ac) * 2);
    }
    __syncthreads();   // all warps done reading Q before buffers are recycled

    attn_cp_tile(smb, K, V, M8, 0, tid); CP_COMMIT();

    float ctx[8][4] = {};
    float rs0 = 0.f, rs1 = 0.f;

    const int br = (lane & 7) + ((lane >> 4) << 3);
    const int bc = ((lane >> 3) & 1) * 8;
    const int mrow_off = (w * 16 + gr) * 64 + gc2;

    for (int kt = 0; kt < 16; kt++) {
        CP_WAIT(0);
        __syncthreads();
        if (kt + 1 < 16) {
            attn_cp_tile(smb + ((kt + 1) & 1) * ABUF_BYTES,
                         K, V, M8, kt + 1, tid);
            CP_COMMIT();
        }

        const uint32_t bb = smb + (kt & 1) * ABUF_BYTES;

        // ---- scores = Q K^T (plain: 1 MMA) ----
        float acc[8][4] = {};
        #pragma unroll
        for (int ks = 0; ks < 4; ks++) {
            #pragma unroll
            for (int ntp = 0; ntp < 4; ntp++) {
                uint32_t k4[4];
                int off = ((ntp * 16 + br) * ATS + ks * 16 + bc) * 2;
                ldsm_x4(k4, bb + off);
                mma_f16(acc[ntp * 2],     qf[ks], &k4[0]);
                mma_f16(acc[ntp * 2 + 1], qf[ks], &k4[2]);
            }
        }

        // ---- e = poly_exp(s/8) * mask (u8 from smem); sums; P frags ----
        const char* mp = sb + (kt & 1) * ABUF_BYTES + AMASK_OFF + mrow_off;
        uint32_t ph[4][4];
        #pragma unroll
        for (int nt = 0; nt < 8; nt++) {
            uint32_t mm01 = *(const uint16_t*)(mp + nt * 8);
            uint32_t mm23 = *(const uint16_t*)(mp + 512 + nt * 8);
            float e0 = fexp8(acc[nt][0]) * (float)(mm01 & 0xFF);
            float e1 = fexp8(acc[nt][1]) * (float)(mm01 >> 8);
            float e2 = fexp8(acc[nt][2]) * (float)(mm23 & 0xFF);
            float e3 = fexp8(acc[nt][3]) * (float)(mm23 >> 8);
            rs0 += e0 + e1;
            rs1 += e2 + e3;
            int u = nt >> 1, sel = (nt & 1) * 2;
            ph[u][sel]     = cvt_f16x2(e0, e1);
            ph[u][sel + 1] = cvt_f16x2(e2, e3);
        }

        // ---- ctx += P V (plain: 1 MMA) ----
        #pragma unroll
        for (int u = 0; u < 4; u++) {
            #pragma unroll
            for (int dtp = 0; dtp < 4; dtp++) {
                uint32_t v4[4];
                int off = ((dtp * 16 + br) * ATS + u * 16 + bc) * 2;
                ldsm_x4(v4, bb + SM_K * 2 + off);
                mma_f16(ctx[dtp * 2],     ph[u], &v4[0]);
                mma_f16(ctx[dtp * 2 + 1], ph[u], &v4[2]);
            }
        }
    }

    // ---- denominators + output ----
    rs0 += __shfl_xor_sync(0xffffffffu, rs0, 1);
    rs0 += __shfl_xor_sync(0xffffffffu, rs0, 2);
    rs1 += __shfl_xor_sync(0xffffffffu, rs1, 1);
    rs1 += __shfl_xor_sync(0xffffffffu, rs1, 2);
    float inv0 = 1.0f / (rs0 + 1e-8f);
    float inv1 = 1.0f / (rs1 + 1e-8f);

    const int s0 = qt * 128 + w * 16 + gr;
    float* O = out + (((size_t)b * SEQ + s0) * NH + h) * HD + gc2;
    #pragma unroll
    for (int dt = 0; dt < 8; dt++) {
        *(float2*)&O[dt * 8] =
            make_float2(ctx[dt][0] * inv0, ctx[dt][1] * inv0);
        *(float2*)&O[(size_t)8 * NH * HD + dt * 8] =
            make_float2(ctx[dt][2] * inv1, ctx[dt][3] * inv1);
    }
}

// ---------------------------------------------------------------------------
extern "C" void kernel_launch(void* const* d_in, const int* in_sizes, int n_in,
                              void* d_out, int out_size)
{
    const float* x    = (const float*)d_in[0];
    const float* mask = (const float*)d_in[1];
    const float* Wq   = (const float*)d_in[2];
    const float* Wk   = (const float*)d_in[3];
    const float* Wv   = (const float*)d_in[4];
    float* out = (float*)d_out;

    static int init = 0;
    if (!init) {
        cudaFuncSetAttribute(qkv_mma_kernel,
            cudaFuncAttributeMaxDynamicSharedMemorySize, QKV_SMEM);
        cudaFuncSetAttribute(attn_mma_kernel,
            cudaFuncAttributeMaxDynamicSharedMemorySize, ATTN_SMEM);
        init = 1;
    }

    convert_x_kernel<<<BATCH * SEQ, 256>>>(x);
    convert_mask_kernel<<<BATCH * SEQ * SEQ / 1024, 256>>>(mask);
    convert_wt_kernel<<<dim3(32, 32, 3), dim3(32, 8)>>>(Wq, Wk, Wv);
    qkv_mma_kernel<<<dim3(64, 8, 3), 256, QKV_SMEM>>>();
    attn_mma_kernel<<<dim3(8, 128), 256, ATTN_SMEM>>>(out);
}